// round 9
// baseline (speedup 1.0000x reference)
#include <cuda_runtime.h>
#include <math.h>

#define B_ 32
#define S_ 512
#define T_ 128
#define H_ 1024
#define H3 3072
#define F2 4096
#define FF 2048
#define V_ 128
#define GRID 144
#define NTHR 256

__device__ float g_Xs[B_*S_*1024];
__device__ float g_Xt[B_*T_*1024];
__device__ float g_enc[B_*S_*512];
__device__ float g_tem[B_*T_*512];
__device__ float g_gie[(size_t)B_*S_*H3];
__device__ float g_gid[(size_t)B_*T_*H3];
__device__ float g_es[(size_t)B_*S_*H_];
__device__ float g_av[(size_t)B_*S_*H_];
__device__ float g_h[B_*H_];
__device__ float g_hd[B_*H_];
__device__ float g_ctA[B_*H_], g_ctB[B_*H_];
__device__ float g_ghp[6*B_*H3];
__device__ float g_cip[6*B_*H3];
__device__ float g_y1p[4*B_*F2];
__device__ float g_y2p[16*B_*FF];
__device__ float g_qp[4*B_*H_];
__device__ float g_sp[8*B_*V_];
__device__ float g_st[512];
__device__ float g_xc[B_*1536];
__device__ unsigned g_cnt;
__device__ volatile unsigned g_gen;

__device__ __forceinline__ void gsync() {
    __syncthreads();
    if (threadIdx.x == 0) {
        __threadfence();
        unsigned gen = g_gen;
        if (atomicAdd(&g_cnt, 1u) == GRID - 1u) {
            g_cnt = 0;
            __threadfence();
            g_gen = gen + 1;
        } else {
            while (g_gen == gen) __nanosleep(64);
        }
        __threadfence();
    }
    __syncthreads();
}

__device__ __forceinline__ float4 loadA(const float* A0, const float* A1, int astr,
    const float* AP, long sstr, int P, const float* ab, int rl, int apN, int ar, int ko)
{
    float4 av;
    if (AP) {
        av = make_float4(0.f, 0.f, 0.f, 0.f);
        for (int p = 0; p < P; p++) {
            float4 u = *(const float4*)&AP[(long)p * sstr + (long)ar * apN + ko];
            av.x += u.x; av.y += u.y; av.z += u.z; av.w += u.w;
        }
        if (ab) { float4 u = *(const float4*)&ab[ko]; av.x += u.x; av.y += u.y; av.z += u.z; av.w += u.w; }
        if (rl) { av.x = fmaxf(av.x, 0.f); av.y = fmaxf(av.y, 0.f); av.z = fmaxf(av.z, 0.f); av.w = fmaxf(av.w, 0.f); }
    } else {
        av = *(const float4*)&A0[(long)ar * astr + ko];
        if (A1) { float4 u = *(const float4*)&A1[(long)ar * astr + ko]; av.x += u.x; av.y += u.y; av.z += u.z; av.w += u.w; }
    }
    return av;
}

// C[b, n0..n0+127] = A[32, k0..k0+klen) @ W[n,:]^T partial. 256 thr.
// lane=b, warp wp owns 16 n. FMA-bound: W smem reads are broadcasts.
__device__ __noinline__ void sgemm(float* SP,
    const float* A0, const float* A1, int astr,
    const float* AP, long sstr, int P, const float* ab, int rl, int apN,
    const float* W, int ldw, int n0, int k0, int klen, float* C, int cN)
{
    float* As = SP;             // [32k][33]: As[k*33+b]
    float* Ws = SP + 1056;      // [128n][36]: Ws[nl*36+k]
    int tid = threadIdx.x, lane = tid & 31, wp = tid >> 5;
    int wr = tid >> 1, wh = (tid & 1) * 16;
    int ar = tid >> 3, kq = (tid & 7) * 4;
    float acc[16] = {};
    float4 w0, w1, w2, w3, av;

    const float* wbase = &W[(long)(n0 + wr) * ldw + wh];
    { const float* p = wbase + k0;
      w0 = *(const float4*)p; w1 = *(const float4*)(p + 4);
      w2 = *(const float4*)(p + 8); w3 = *(const float4*)(p + 12); }
    av = loadA(A0, A1, astr, AP, sstr, P, ab, rl, apN, ar, k0 + kq);

    for (int kk = k0; kk < k0 + klen; kk += 32) {
        __syncthreads();
        float* wd = &Ws[wr * 36 + wh];
        *(float4*)wd = w0; *(float4*)(wd + 4) = w1;
        *(float4*)(wd + 8) = w2; *(float4*)(wd + 12) = w3;
        As[(kq + 0) * 33 + ar] = av.x; As[(kq + 1) * 33 + ar] = av.y;
        As[(kq + 2) * 33 + ar] = av.z; As[(kq + 3) * 33 + ar] = av.w;
        __syncthreads();
        int kn = kk + 32;
        if (kn < k0 + klen) {
            const float* p = wbase + kn;
            w0 = *(const float4*)p; w1 = *(const float4*)(p + 4);
            w2 = *(const float4*)(p + 8); w3 = *(const float4*)(p + 12);
            av = loadA(A0, A1, astr, AP, sstr, P, ab, rl, apN, ar, kn + kq);
        }
        const float* wrow = &Ws[wp * 16 * 36];
#pragma unroll
        for (int k4 = 0; k4 < 8; k4++) {
            float a0 = As[(k4 * 4 + 0) * 33 + lane];
            float a1 = As[(k4 * 4 + 1) * 33 + lane];
            float a2 = As[(k4 * 4 + 2) * 33 + lane];
            float a3 = As[(k4 * 4 + 3) * 33 + lane];
#pragma unroll
            for (int j = 0; j < 16; j++) {
                float4 wv = *(const float4*)&wrow[j * 36 + k4 * 4];
                acc[j] = fmaf(a0, wv.x, acc[j]);
                acc[j] = fmaf(a1, wv.y, acc[j]);
                acc[j] = fmaf(a2, wv.z, acc[j]);
                acc[j] = fmaf(a3, wv.w, acc[j]);
            }
        }
    }
    __syncthreads();
#pragma unroll
    for (int j = 0; j < 16; j++) SP[lane * 132 + wp * 16 + j] = acc[j];
    __syncthreads();
    int sb = tid >> 3, sq = (tid & 7) * 4;
#pragma unroll
    for (int i = 0; i < 4; i++) {
        int nn = i * 32 + sq;
        *(float4*)&C[(long)sb * cN + n0 + nn] = *(float4*)&SP[sb * 132 + nn];
    }
}

__global__ void gather_k(const int* __restrict__ ch, const int* __restrict__ lg,
                         const float* __restrict__ ce, const float* __restrict__ le,
                         float* __restrict__ X, int ntok) {
    long i = (long)blockIdx.x * 256 + threadIdx.x;
    if (i >= (long)ntok * 1024) return;
    int tok = (int)(i >> 10), c = (int)(i & 1023);
    X[i] = (c < 512) ? ce[ch[tok] * 512 + c] : le[(lg ? lg[tok] : 4) * 512 + (c - 512)];
}

__global__ void startemb_k(const float* __restrict__ ce, const float* __restrict__ le,
                           const float* __restrict__ fcW, const float* __restrict__ fcb,
                           float* __restrict__ o) {
    int g = blockIdx.x * 8 + (threadIdx.x >> 5), l = threadIdx.x & 31;
    float a = 0.f;
    for (int k = l; k < 1024; k += 32)
        a += ((k < 512) ? ce[512 + k] : le[2048 + (k - 512)]) * fcW[g * 1024 + k];
#pragma unroll
    for (int s = 16; s; s >>= 1) a += __shfl_down_sync(~0u, a, s);
    if (!l) o[g] = a + fcb[g];
}

__global__ void gemm_nt(const float* __restrict__ A, int lda,
                        const float* __restrict__ W, int ldw,
                        const float* __restrict__ bias,
                        float* __restrict__ C, int ldc, int K, int accf) {
    __shared__ float As[8][128], Ws[8][128];
    int bm = blockIdx.y * 128, bn = blockIdx.x * 128, tid = threadIdx.x;
    int lr = tid >> 1, lc = (tid & 1) * 4, tx = tid & 15, ty = tid >> 4;
    float acc[8][8] = {};
    for (int k0 = 0; k0 < K; k0 += 8) {
        float4 a = *(const float4*)&A[(long)(bm + lr) * lda + k0 + lc];
        float4 w = *(const float4*)&W[(long)(bn + lr) * ldw + k0 + lc];
        As[lc][lr] = a.x; As[lc+1][lr] = a.y; As[lc+2][lr] = a.z; As[lc+3][lr] = a.w;
        Ws[lc][lr] = w.x; Ws[lc+1][lr] = w.y; Ws[lc+2][lr] = w.z; Ws[lc+3][lr] = w.w;
        __syncthreads();
#pragma unroll
        for (int k = 0; k < 8; k++) {
            float avv[8], bv[8];
            *(float4*)avv = *(const float4*)&As[k][ty*8]; *(float4*)(avv+4) = *(const float4*)&As[k][ty*8+4];
            *(float4*)bv = *(const float4*)&Ws[k][tx*8]; *(float4*)(bv+4) = *(const float4*)&Ws[k][tx*8+4];
#pragma unroll
            for (int i = 0; i < 8; i++)
#pragma unroll
                for (int j = 0; j < 8; j++) acc[i][j] = fmaf(avv[i], bv[j], acc[i][j]);
        }
        __syncthreads();
    }
#pragma unroll
    for (int i = 0; i < 8; i++) {
        long row = bm + ty * 8 + i;
#pragma unroll
        for (int j = 0; j < 8; j += 4) {
            int col = bn + tx * 8 + j;
            float4 v = make_float4(acc[i][j], acc[i][j+1], acc[i][j+2], acc[i][j+3]);
            if (bias) { v.x += bias[col]; v.y += bias[col+1]; v.z += bias[col+2]; v.w += bias[col+3]; }
            float4* cp = (float4*)&C[row * ldc + col];
            if (accf) { float4 o = *cp; v.x += o.x; v.y += o.y; v.z += o.z; v.w += o.w; }
            *cp = v;
        }
    }
}

__global__ void __launch_bounds__(NTHR, 1) enc_pk(const float* __restrict__ Wh,
                                                  const float* __restrict__ bh) {
    __shared__ float SP[5664];
    int bid = blockIdx.x, tid = threadIdx.x;
    for (int i = bid * NTHR + tid; i < B_ * H_; i += GRID * NTHR) g_h[i] = 0.f;
    gsync();
    const int kb[7] = {0, 192, 384, 544, 704, 864, 1024};
    int nt = bid / 6, ks = bid % 6;
    for (int t = 0; t < S_; t++) {
        sgemm(SP, g_h, 0, H_, 0, 0, 0, 0, 0, 0, Wh, H_, nt * 128, kb[ks], kb[ks+1] - kb[ks],
              g_ghp + (long)ks * B_ * H3, H3);
        gsync();
        for (int i = bid * NTHR + tid; i < B_ * H_; i += GRID * NTHR) {
            int b = i >> 10, j = i & 1023;
            const float* gi = &g_gie[((size_t)(b * S_ + t)) * H3];
            float ir = gi[j], iz = gi[j + H_], in = gi[j + 2*H_];
            float hr = bh[j], hz = bh[j + H_], hn = bh[j + 2*H_];
            for (int p = 0; p < 6; p++) {
                const float* gp = &g_ghp[(long)p * B_ * H3 + (long)b * H3];
                hr += gp[j]; hz += gp[j + H_]; hn += gp[j + 2*H_];
            }
            float ho = g_h[i];
            float r = 1.f / (1.f + expf(-(ir + hr)));
            float z = 1.f / (1.f + expf(-(iz + hz)));
            float n = tanhf(in + r * hn);
            float hv = (1.f - z) * n + z * ho;
            g_h[i] = hv;
            g_es[((size_t)(b * S_ + t)) * H_ + j] = hv;
        }
        gsync();
    }
}

__global__ void __launch_bounds__(NTHR, 1) dec_pk(
    const float* __restrict__ Wi, const float* __restrict__ Wh,
    const float* __restrict__ bi, const float* __restrict__ bh,
    const float* __restrict__ Wq, const float* __restrict__ W1, const float* __restrict__ b1,
    const float* __restrict__ W2, const float* __restrict__ b2, const float* __restrict__ W3,
    float* __restrict__ out) {
    __shared__ float SP[5664];
    int bid = blockIdx.x, tid = threadIdx.x;
    for (int i = bid * NTHR + tid; i < B_ * 1536; i += GRID * NTHR) {
        int b = i / 1536, k = i % 1536;
        float v = (k < 512) ? g_st[k] : g_es[((size_t)(b * S_ + S_ - 1)) * H_ + k - 512];
        if (k >= 512) g_ctA[b * H_ + k - 512] = v;
        g_xc[i] = v;
    }
    gsync();
    { int nt = bid / 6, ks = bid % 6;
      sgemm(SP, g_xc, 0, 1536, 0, 0, 0, 0, 0, 0, Wi, 1536, nt * 128, ks * 256, 256,
            g_cip + (long)ks * B_ * H3, H3); }
    gsync();
    for (int i = bid * NTHR + tid; i < B_ * H_; i += GRID * NTHR) {
        int b = i >> 10, j = i & 1023;
        float ir = bi[j], iz = bi[j + H_], in = bi[j + 2*H_];
        for (int p = 0; p < 6; p++) {
            const float* gp = &g_cip[(long)p * B_ * H3 + (long)b * H3];
            ir += gp[j]; iz += gp[j + H_]; in += gp[j + 2*H_];
        }
        float hr = bh[j], hz = bh[j + H_], hn = bh[j + 2*H_];
        float r = 1.f / (1.f + expf(-(ir + hr)));
        float z = 1.f / (1.f + expf(-(iz + hz)));
        float n = tanhf(in + r * hn);
        g_hd[i] = (1.f - z) * n;
    }
    gsync();
    const int kcb[6] = {0, 224, 448, 640, 832, 1024};
    for (int t = 0; t < T_; t++) {
        const float* cp = (t & 1) ? g_ctB : g_ctA;
        float* cn = (t & 1) ? g_ctA : g_ctB;
        for (int it = bid; it < 256; it += GRID) {           // S1: y1p, qp, ghp
            if (it < 128) { int nt = it >> 2, ks = it & 3;
                sgemm(SP, g_hd, cp, H_, 0,0,0,0,0,0, W1, H_, nt*128, ks*256, 256, g_y1p + (long)ks*B_*F2, F2); }
            else if (it < 160) { int i2 = it - 128, nt = i2 >> 2, ks = i2 & 3;
                sgemm(SP, g_hd, 0, H_, 0,0,0,0,0,0, Wq, H_, nt*128, ks*256, 256, g_qp + (long)ks*B_*H_, H_); }
            else { int i2 = it - 160, nt = i2 >> 2, ks = i2 & 3;
                sgemm(SP, g_hd, 0, H_, 0,0,0,0,0,0, Wh, H_, nt*128, ks*256, 256, g_ghp + (long)ks*B_*H3, H3); }
        }
        gsync();
        for (int it = bid; it < 288; it += GRID) {           // S2: y2p + fused attention
            if (it < 256) { int nt = it >> 4, ks = it & 15;
                sgemm(SP, 0,0,0, g_y1p, (long)B_*F2, 4, b1, 1, F2, W2, F2, nt*128, ks*256, 256,
                      g_y2p + (long)ks*B_*FF, FF); }
            else {
                int b = it - 256;
                float* q = SP; float* lg = SP + 1024; float* red = SP + 1536;
                __syncthreads();
                for (int i = tid; i < H_; i += NTHR) {
                    float s = 0.f;
                    for (int p = 0; p < 4; p++) s += g_qp[(long)p*B_*H_ + b*H_ + i];
                    q[i] = s;
                }
                __syncthreads();
                int w = tid >> 5, l = tid & 31;
                for (int s = w; s < S_; s += 8) {
                    const float* e = &g_es[((size_t)(b * S_ + s)) * H_];
                    float a = 0.f;
#pragma unroll
                    for (int m = 0; m < 8; m++) {
                        float4 ev = *(const float4*)&e[m*128 + l*4];
                        float4 qv = *(const float4*)&q[m*128 + l*4];
                        a += ev.x*qv.x + ev.y*qv.y + ev.z*qv.z + ev.w*qv.w;
                    }
#pragma unroll
                    for (int o = 16; o; o >>= 1) a += __shfl_down_sync(~0u, a, o);
                    if (!l) lg[s] = a;
                }
                __syncthreads();
                float v0 = lg[tid], v1 = lg[tid + 256];
                red[tid] = fmaxf(v0, v1); __syncthreads();
                for (int s = 128; s; s >>= 1) { if (tid < s) red[tid] = fmaxf(red[tid], red[tid+s]); __syncthreads(); }
                float mx = red[0]; __syncthreads();
                float e0 = expf(v0 - mx), e1 = expf(v1 - mx);
                red[tid] = e0 + e1; __syncthreads();
                for (int s = 128; s; s >>= 1) { if (tid < s) red[tid] += red[tid+s]; __syncthreads(); }
                float inv = 1.f / red[0]; __syncthreads();
                lg[tid] = e0 * inv; lg[tid + 256] = e1 * inv;
                __syncthreads();
                float a0 = 0.f, a1 = 0.f, a2 = 0.f, a3 = 0.f;
#pragma unroll 4
                for (int s = 0; s < S_; s++) {
                    float ws = lg[s];
                    const float* r = &g_av[((size_t)(b * S_ + s)) * H_];
                    a0 += ws * r[tid]; a1 += ws * r[tid + 256];
                    a2 += ws * r[tid + 512]; a3 += ws * r[tid + 768];
                }
                cn[b*H_ + tid] = a0; cn[b*H_ + tid + 256] = a1;
                cn[b*H_ + tid + 512] = a2; cn[b*H_ + tid + 768] = a3;
                __syncthreads();
            }
        }
        gsync();
        for (int it = bid; it < 128; it += GRID) {           // S3: cip (ctx) + sp (W3)
            if (it < 120) { int nt = it / 5, ks = it % 5;
                sgemm(SP, cn, 0, H_, 0,0,0,0,0,0, Wi + 512, 1536, nt*128, kcb[ks], kcb[ks+1]-kcb[ks],
                      g_cip + (long)ks*B_*H3, H3); }
            else { int ks = it - 120;
                sgemm(SP, 0,0,0, g_y2p, (long)B_*FF, 16, b2, 1, FF, W3, FF, 0, ks*256, 256,
                      g_sp + (long)ks*B_*V_, V_); }
        }
        gsync();
        for (int i = bid * NTHR + tid; i < B_ * H_; i += GRID * NTHR) {   // S4: gates
            int b = i >> 10, j = i & 1023;
            const float* gi = &g_gid[((size_t)(b * T_ + t)) * H3];
            float ir = gi[j], iz = gi[j + H_], in = gi[j + 2*H_];
            for (int p = 0; p < 5; p++) {
                const float* gp = &g_cip[(long)p*B_*H3 + (long)b*H3];
                ir += gp[j]; iz += gp[j + H_]; in += gp[j + 2*H_];
            }
            float hr = bh[j], hz = bh[j + H_], hn = bh[j + 2*H_];
            for (int p = 0; p < 4; p++) {
                const float* gp = &g_ghp[(long)p*B_*H3 + (long)b*H3];
                hr += gp[j]; hz += gp[j + H_]; hn += gp[j + 2*H_];
            }
            float ho = g_hd[i];
            float r = 1.f / (1.f + expf(-(ir + hr)));
            float z = 1.f / (1.f + expf(-(iz + hz)));
            float n = tanhf(in + r * hn);
            g_hd[i] = (1.f - z) * n + z * ho;
        }
        for (int i = bid * NTHR + tid; i < B_ * V_; i += GRID * NTHR) {   // scores out
            int b = i >> 7, v = i & 127;
            float s = 0.f;
            for (int p = 0; p < 8; p++) s += g_sp[p*B_*V_ + b*V_ + v];
            out[((size_t)(b * T_ + t)) * V_ + v] = s;
        }
        gsync();
    }
}

static float* sym(const void* s) { void* p = 0; cudaGetSymbolAddress(&p, s); return (float*)p; }

extern "C" void kernel_launch(void* const* d_in, const int*, int, void* d_out, int) {
    const int* sc = (const int*)d_in[0];  const int* sl = (const int*)d_in[1];
    const int* tc = (const int*)d_in[2];
    const float* ce = (const float*)d_in[3];  const float* le = (const float*)d_in[4];
    const float* fcW = (const float*)d_in[5]; const float* fcb = (const float*)d_in[6];
    const float* eWi = (const float*)d_in[7]; const float* eWh = (const float*)d_in[8];
    const float* ebi = (const float*)d_in[9]; const float* ebh = (const float*)d_in[10];
    const float* dWi = (const float*)d_in[11]; const float* dWh = (const float*)d_in[12];
    const float* dbi = (const float*)d_in[13]; const float* dbh = (const float*)d_in[14];
    const float* Wq = (const float*)d_in[15]; const float* Wk = (const float*)d_in[16];
    const float* Wcs = (const float*)d_in[17];
    const float* W1 = (const float*)d_in[18]; const float* b1 = (const float*)d_in[19];
    const float* W2 = (const float*)d_in[20]; const float* b2 = (const float*)d_in[21];
    const float* W3 = (const float*)d_in[22];
    float* out = (float*)d_out;
    float *Xs = sym(g_Xs), *Xt = sym(g_Xt), *enc = sym(g_enc), *tem = sym(g_tem),
          *gie = sym(g_gie), *gid = sym(g_gid), *es = sym(g_es), *av = sym(g_av), *st = sym(g_st);

    gather_k<<<(B_*S_*1024)/256, 256>>>(sc, sl, ce, le, Xs, B_*S_);
    gather_k<<<(B_*T_*1024)/256, 256>>>(tc, 0, ce, le, Xt, B_*T_);
    gemm_nt<<<dim3(4, B_*S_/128), 256>>>(Xs, 1024, fcW, 1024, fcb, enc, 512, 1024, 0);
    gemm_nt<<<dim3(4, B_*T_/128), 256>>>(Xt, 1024, fcW, 1024, fcb, tem, 512, 1024, 0);
    gemm_nt<<<dim3(H3/128, B_*S_/128), 256>>>(enc, 512, eWi, 512, ebi, gie, H3, 512, 0);
    gemm_nt<<<dim3(H3/128, B_*T_/128), 256>>>(tem, 512, dWi, 1536, dbi, gid, H3, 512, 0);
    gemm_nt<<<dim3(H_/128, B_*S_/128), 256>>>(enc, 512, Wcs, 512, 0, av, H_, 512, 0);
    startemb_k<<<64, 256>>>(ce, le, fcW, fcb, st);
    enc_pk<<<GRID, NTHR>>>(eWh, ebh);
    gemm_nt<<<dim3(H_/128, B_*S_/128), 256>>>(es, H_, Wk, H_, 0, av, H_, 1024, 1);
    dec_pk<<<GRID, NTHR>>>(dWi, dWh, dbi, dbh, Wq, W1, b1, W2, b2, W3, out);
}

// round 10
// speedup vs baseline: 1.1731x; 1.1731x over previous
#include <cuda_runtime.h>
#include <cuda_bf16.h>
#include <math.h>

#define B_ 32
#define S_ 512
#define T_ 128
#define H_ 1024
#define H3 3072
#define F2 4096
#define FF 2048
#define V_ 128
#define GRID 144
#define NTHR 256

__device__ float g_Xs[B_*S_*1024];
__device__ float g_Xt[B_*T_*1024];
__device__ float g_enc[B_*S_*512];
__device__ float g_tem[B_*T_*512];
__device__ float g_gie[(size_t)B_*S_*H3];
__device__ float g_gid[(size_t)B_*T_*H3];
__device__ float g_es[(size_t)B_*S_*H_];
__device__ float g_av[(size_t)B_*S_*H_];
__device__ __nv_bfloat16 g_es16[(size_t)B_*S_*H_];
__device__ __nv_bfloat16 g_av16[(size_t)B_*S_*H_];
__device__ float g_h[B_*H_];
__device__ float g_hd[B_*H_];
__device__ float g_ctA[B_*H_], g_ctB[B_*H_];
__device__ float g_ghp[6*B_*H3];
__device__ float g_cip[6*B_*H3];
__device__ float g_y1p[4*B_*F2];
__device__ float g_y2p[16*B_*FF];
__device__ float g_qp[4*B_*H_];
__device__ float g_sp[8*B_*V_];
__device__ float g_att[B_*S_];
__device__ float g_st[512];
__device__ float g_xc[B_*1536];
__device__ unsigned g_cnt;
__device__ volatile unsigned g_gen;

__device__ __forceinline__ void gsync() {
    __syncthreads();
    if (threadIdx.x == 0) {
        __threadfence();
        unsigned gen = g_gen;
        if (atomicAdd(&g_cnt, 1u) == GRID - 1u) {
            g_cnt = 0;
            __threadfence();
            g_gen = gen + 1;
        } else {
            while (g_gen == gen) __nanosleep(64);
        }
        __threadfence();
    }
    __syncthreads();
}

// ---- R8-proven skinny GEMM: C[32b, n0..n0+127] partial over [k0,k0+klen). 256 thr, 4b x 4n.
__device__ __noinline__ void sgemm(float* SP,
    const float* A0, const float* A1, int astr,
    const float* AP, long sstr, int P, const float* ab, int rl, int apN,
    const float* W, int ldw, int n0, int k0, int klen, float* C, int cN)
{
    float* As = SP;            // [32k][36]
    float* Ws = SP + 1152;     // [32k][132]
    int tid = threadIdx.x, bq = tid >> 5, nq = tid & 31;
    float ac[4][4] = {};
    for (int kk = k0; kk < k0 + klen; kk += 32) {
        __syncthreads();
        {
            int b = tid >> 3, kq = tid & 7, ko = kk + kq * 4;
            float4 v;
            if (AP) {
                v = make_float4(0.f, 0.f, 0.f, 0.f);
                for (int p = 0; p < P; p++) {
                    float4 u = *(const float4*)&AP[(long)p * sstr + (long)b * apN + ko];
                    v.x += u.x; v.y += u.y; v.z += u.z; v.w += u.w;
                }
                if (ab) { float4 u = *(const float4*)&ab[ko]; v.x += u.x; v.y += u.y; v.z += u.z; v.w += u.w; }
                if (rl) { v.x = fmaxf(v.x, 0.f); v.y = fmaxf(v.y, 0.f); v.z = fmaxf(v.z, 0.f); v.w = fmaxf(v.w, 0.f); }
            } else {
                v = *(const float4*)&A0[(long)b * astr + ko];
                if (A1) { float4 u = *(const float4*)&A1[(long)b * astr + ko]; v.x += u.x; v.y += u.y; v.z += u.z; v.w += u.w; }
            }
            As[(kq*4+0)*36+b] = v.x; As[(kq*4+1)*36+b] = v.y;
            As[(kq*4+2)*36+b] = v.z; As[(kq*4+3)*36+b] = v.w;
        }
#pragma unroll
        for (int it = 0; it < 4; it++) {
            int r = nq + it * 32;
            float4 v = *(const float4*)&W[(long)(n0 + r) * ldw + kk + bq * 4];
            Ws[(bq*4+0)*132+r] = v.x; Ws[(bq*4+1)*132+r] = v.y;
            Ws[(bq*4+2)*132+r] = v.z; Ws[(bq*4+3)*132+r] = v.w;
        }
        __syncthreads();
#pragma unroll
        for (int k = 0; k < 32; k++) {
            float4 a = *(const float4*)&As[k*36 + bq*4];
            float4 w = *(const float4*)&Ws[k*132 + nq*4];
            float avv[4] = {a.x, a.y, a.z, a.w}, wv[4] = {w.x, w.y, w.z, w.w};
#pragma unroll
            for (int i = 0; i < 4; i++)
#pragma unroll
                for (int j = 0; j < 4; j++) ac[i][j] = fmaf(avv[i], wv[j], ac[i][j]);
        }
    }
#pragma unroll
    for (int i = 0; i < 4; i++)
        *(float4*)&C[(long)(bq*4+i)*cN + n0 + nq*4] = *(float4*)ac[i];
}

__global__ void gather_k(const int* __restrict__ ch, const int* __restrict__ lg,
                         const float* __restrict__ ce, const float* __restrict__ le,
                         float* __restrict__ X, int ntok) {
    long i = (long)blockIdx.x * 256 + threadIdx.x;
    if (i >= (long)ntok * 1024) return;
    int tok = (int)(i >> 10), c = (int)(i & 1023);
    X[i] = (c < 512) ? ce[ch[tok] * 512 + c] : le[(lg ? lg[tok] : 4) * 512 + (c - 512)];
}

__global__ void startemb_k(const float* __restrict__ ce, const float* __restrict__ le,
                           const float* __restrict__ fcW, const float* __restrict__ fcb,
                           float* __restrict__ o) {
    int g = blockIdx.x * 8 + (threadIdx.x >> 5), l = threadIdx.x & 31;
    float a = 0.f;
    for (int k = l; k < 1024; k += 32)
        a += ((k < 512) ? ce[512 + k] : le[2048 + (k - 512)]) * fcW[g * 1024 + k];
#pragma unroll
    for (int s = 16; s; s >>= 1) a += __shfl_down_sync(~0u, a, s);
    if (!l) o[g] = a + fcb[g];
}

__global__ void tobf16_k(const float* __restrict__ src, __nv_bfloat16* __restrict__ dst, long n) {
    long i = (long)blockIdx.x * 256 + threadIdx.x;
    if (i < n) dst[i] = __float2bfloat16(src[i]);
}

__global__ void gemm_nt(const float* __restrict__ A, int lda,
                        const float* __restrict__ W, int ldw,
                        const float* __restrict__ bias,
                        float* __restrict__ C, int ldc, int K, int accf) {
    __shared__ float As[8][128], Ws[8][128];
    int bm = blockIdx.y * 128, bn = blockIdx.x * 128, tid = threadIdx.x;
    int lr = tid >> 1, lc = (tid & 1) * 4, tx = tid & 15, ty = tid >> 4;
    float acc[8][8] = {};
    for (int k0 = 0; k0 < K; k0 += 8) {
        float4 a = *(const float4*)&A[(long)(bm + lr) * lda + k0 + lc];
        float4 w = *(const float4*)&W[(long)(bn + lr) * ldw + k0 + lc];
        As[lc][lr] = a.x; As[lc+1][lr] = a.y; As[lc+2][lr] = a.z; As[lc+3][lr] = a.w;
        Ws[lc][lr] = w.x; Ws[lc+1][lr] = w.y; Ws[lc+2][lr] = w.z; Ws[lc+3][lr] = w.w;
        __syncthreads();
#pragma unroll
        for (int k = 0; k < 8; k++) {
            float avv[8], bv[8];
            *(float4*)avv = *(const float4*)&As[k][ty*8]; *(float4*)(avv+4) = *(const float4*)&As[k][ty*8+4];
            *(float4*)bv = *(const float4*)&Ws[k][tx*8]; *(float4*)(bv+4) = *(const float4*)&Ws[k][tx*8+4];
#pragma unroll
            for (int i = 0; i < 8; i++)
#pragma unroll
                for (int j = 0; j < 8; j++) acc[i][j] = fmaf(avv[i], bv[j], acc[i][j]);
        }
        __syncthreads();
    }
#pragma unroll
    for (int i = 0; i < 8; i++) {
        long row = bm + ty * 8 + i;
#pragma unroll
        for (int j = 0; j < 8; j += 4) {
            int col = bn + tx * 8 + j;
            float4 v = make_float4(acc[i][j], acc[i][j+1], acc[i][j+2], acc[i][j+3]);
            if (bias) { v.x += bias[col]; v.y += bias[col+1]; v.z += bias[col+2]; v.w += bias[col+3]; }
            float4* cp = (float4*)&C[row * ldc + col];
            if (accf) { float4 o = *cp; v.x += o.x; v.y += o.y; v.z += o.z; v.w += o.w; }
            *cp = v;
        }
    }
}

__global__ void __launch_bounds__(NTHR, 1) enc_pk(const float* __restrict__ Wh,
                                                  const float* __restrict__ bh) {
    __shared__ float SP[5664];
    int bid = blockIdx.x, tid = threadIdx.x;
    for (int i = bid * NTHR + tid; i < B_ * H_; i += GRID * NTHR) g_h[i] = 0.f;
    gsync();
    const int kb[7] = {0, 192, 384, 544, 704, 864, 1024};
    int nt = bid / 6, ks = bid % 6;
    for (int t = 0; t < S_; t++) {
        sgemm(SP, g_h, 0, H_, 0, 0, 0, 0, 0, 0, Wh, H_, nt * 128, kb[ks], kb[ks+1] - kb[ks],
              g_ghp + (long)ks * B_ * H3, H3);
        gsync();
        for (int i = bid * NTHR + tid; i < B_ * H_; i += GRID * NTHR) {
            int b = i >> 10, j = i & 1023;
            const float* gi = &g_gie[((size_t)(b * S_ + t)) * H3];
            float ir = gi[j], iz = gi[j + H_], in = gi[j + 2*H_];
            float hr = bh[j], hz = bh[j + H_], hn = bh[j + 2*H_];
            for (int p = 0; p < 6; p++) {
                const float* gp = &g_ghp[(long)p * B_ * H3 + (long)b * H3];
                hr += gp[j]; hz += gp[j + H_]; hn += gp[j + 2*H_];
            }
            float ho = g_h[i];
            float r = 1.f / (1.f + expf(-(ir + hr)));
            float z = 1.f / (1.f + expf(-(iz + hz)));
            float n = tanhf(in + r * hn);
            float hv = (1.f - z) * n + z * ho;
            g_h[i] = hv;
            g_es[((size_t)(b * S_ + t)) * H_ + j] = hv;
        }
        gsync();
    }
}

__global__ void __launch_bounds__(NTHR, 1) dec_pk(
    const float* __restrict__ Wi, const float* __restrict__ Wh,
    const float* __restrict__ bi, const float* __restrict__ bh,
    const float* __restrict__ Wq, const float* __restrict__ W1, const float* __restrict__ b1,
    const float* __restrict__ W2, const float* __restrict__ b2, const float* __restrict__ W3,
    float* __restrict__ out) {
    __shared__ float SP[5664];
    int bid = blockIdx.x, tid = threadIdx.x;
    for (int i = bid * NTHR + tid; i < B_ * 1536; i += GRID * NTHR) {
        int b = i / 1536, k = i % 1536;
        float v = (k < 512) ? g_st[k] : g_es[((size_t)(b * S_ + S_ - 1)) * H_ + k - 512];
        if (k >= 512) g_ctA[b * H_ + k - 512] = v;
        g_xc[i] = v;
    }
    gsync();
    { int nt = bid / 6, ks = bid % 6;
      sgemm(SP, g_xc, 0, 1536, 0, 0, 0, 0, 0, 0, Wi, 1536, nt * 128, ks * 256, 256,
            g_cip + (long)ks * B_ * H3, H3); }
    gsync();
    for (int i = bid * NTHR + tid; i < B_ * H_; i += GRID * NTHR) {
        int b = i >> 10, j = i & 1023;
        float ir = bi[j], iz = bi[j + H_], in = bi[j + 2*H_];
        for (int p = 0; p < 6; p++) {
            const float* gp = &g_cip[(long)p * B_ * H3 + (long)b * H3];
            ir += gp[j]; iz += gp[j + H_]; in += gp[j + 2*H_];
        }
        float hr = bh[j], hz = bh[j + H_], hn = bh[j + 2*H_];
        float r = 1.f / (1.f + expf(-(ir + hr)));
        float z = 1.f / (1.f + expf(-(iz + hz)));
        float n = tanhf(in + r * hn);
        g_hd[i] = (1.f - z) * n;
    }
    gsync();
    for (int t = 0; t < T_; t++) {
        const float* cp = (t & 1) ? g_ctB : g_ctA;
        float* cn = (t & 1) ? g_ctA : g_ctB;
        for (int it = bid; it < 256; it += GRID) {           // S1: y1p, qp, ghp
            if (it < 128) { int nt = it >> 2, ks = it & 3;
                sgemm(SP, g_hd, cp, H_, 0,0,0,0,0,0, W1, H_, nt*128, ks*256, 256, g_y1p + (long)ks*B_*F2, F2); }
            else if (it < 160) { int i2 = it - 128, nt = i2 >> 2, ks = i2 & 3;
                sgemm(SP, g_hd, 0, H_, 0,0,0,0,0,0, Wq, H_, nt*128, ks*256, 256, g_qp + (long)ks*B_*H_, H_); }
            else { int i2 = it - 160, nt = i2 >> 2, ks = i2 & 3;
                sgemm(SP, g_hd, 0, H_, 0,0,0,0,0,0, Wh, H_, nt*128, ks*256, 256, g_ghp + (long)ks*B_*H3, H3); }
        }
        gsync();
        for (int it = bid; it < 288; it += GRID) {           // S2: y2p + att logits (bf16 es)
            if (it < 256) { int nt = it >> 4, ks = it & 15;
                sgemm(SP, 0,0,0, g_y1p, (long)B_*F2, 4, b1, 1, F2, W2, F2, nt*128, ks*256, 256,
                      g_y2p + (long)ks*B_*FF, FF); }
            else {
                int b = it - 256;
                float* q = SP;
                __syncthreads();
                for (int i = tid; i < H_; i += NTHR) {
                    float s = 0.f;
                    for (int p = 0; p < 4; p++) s += g_qp[(long)p*B_*H_ + b*H_ + i];
                    q[i] = s;
                }
                __syncthreads();
                int w = tid >> 5, l = tid & 31;
                for (int s = w; s < S_; s += 8) {
                    const __nv_bfloat16* e = &g_es16[((size_t)(b * S_ + s)) * H_];
                    float a = 0.f;
#pragma unroll
                    for (int m = 0; m < 4; m++) {
                        const __nv_bfloat162* e2 = (const __nv_bfloat162*)&e[m*256 + l*8];
                        const float* qq = &q[m*256 + l*8];
#pragma unroll
                        for (int u = 0; u < 4; u++) {
                            float2 p = __bfloat1622float2(e2[u]);
                            a += p.x * qq[u*2] + p.y * qq[u*2+1];
                        }
                    }
#pragma unroll
                    for (int o = 16; o; o >>= 1) a += __shfl_down_sync(~0u, a, o);
                    if (!l) g_att[b * S_ + s] = a;
                }
                __syncthreads();
            }
        }
        gsync();
        for (int it = bid; it < 136; it += GRID) {           // S3: softmax+ctx (bf16 av) + sp
            if (it < 128) {
                int b = it >> 2, hq = it & 3;
                float* red = SP + 512;
                __syncthreads();
                float v0 = g_att[b*S_ + tid], v1 = g_att[b*S_ + 256 + tid];
                red[tid] = fmaxf(v0, v1); __syncthreads();
                for (int s = 128; s; s >>= 1) { if (tid < s) red[tid] = fmaxf(red[tid], red[tid+s]); __syncthreads(); }
                float mx = red[0]; __syncthreads();
                float e0 = expf(v0 - mx), e1 = expf(v1 - mx);
                red[tid] = e0 + e1; __syncthreads();
                for (int s = 128; s; s >>= 1) { if (tid < s) red[tid] += red[tid+s]; __syncthreads(); }
                float inv = 1.f / red[0]; __syncthreads();
                SP[tid] = e0 * inv; SP[tid + 256] = e1 * inv;
                __syncthreads();
                int hc = hq * 256 + tid;
                const __nv_bfloat16* a = &g_av16[((size_t)b * S_) * H_ + hc];
                float acc = 0.f;
#pragma unroll 8
                for (int s = 0; s < S_; s++) acc += SP[s] * __bfloat162float(a[(size_t)s * H_]);
                cn[b * H_ + hc] = acc;
                __syncthreads();
            } else { int ks = it - 128;
                sgemm(SP, 0,0,0, g_y2p, (long)B_*FF, 16, b2, 1, FF, W3, FF, 0, ks*256, 256,
                      g_sp + (long)ks*B_*V_, V_); }
        }
        gsync();
        for (int it = bid; it < 96; it += GRID) {            // S4: cip (ctx GEMM)
            int nt = it >> 2, ks = it & 3;
            sgemm(SP, cn, 0, H_, 0,0,0,0,0,0, Wi + 512, 1536, nt*128, ks*256, 256,
                  g_cip + (long)ks*B_*H3, H3);
        }
        gsync();
        for (int i = bid * NTHR + tid; i < B_ * H_; i += GRID * NTHR) {   // S5: gates
            int b = i >> 10, j = i & 1023;
            const float* gi = &g_gid[((size_t)(b * T_ + t)) * H3];
            float ir = gi[j], iz = gi[j + H_], in = gi[j + 2*H_];
            for (int p = 0; p < 4; p++) {
                const float* gp = &g_cip[(long)p*B_*H3 + (long)b*H3];
                ir += gp[j]; iz += gp[j + H_]; in += gp[j + 2*H_];
            }
            float hr = bh[j], hz = bh[j + H_], hn = bh[j + 2*H_];
            for (int p = 0; p < 4; p++) {
                const float* gp = &g_ghp[(long)p*B_*H3 + (long)b*H3];
                hr += gp[j]; hz += gp[j + H_]; hn += gp[j + 2*H_];
            }
            float ho = g_hd[i];
            float r = 1.f / (1.f + expf(-(ir + hr)));
            float z = 1.f / (1.f + expf(-(iz + hz)));
            float n = tanhf(in + r * hn);
            g_hd[i] = (1.f - z) * n + z * ho;
        }
        for (int i = bid * NTHR + tid; i < B_ * V_; i += GRID * NTHR) {
            int b = i >> 7, v = i & 127;
            float s = 0.f;
            for (int p = 0; p < 8; p++) s += g_sp[p*B_*V_ + b*V_ + v];
            out[((size_t)(b * T_ + t)) * V_ + v] = s;
        }
        gsync();
    }
}

static float* sym(const void* s) { void* p = 0; cudaGetSymbolAddress(&p, s); return (float*)p; }

extern "C" void kernel_launch(void* const* d_in, const int*, int, void* d_out, int) {
    const int* sc = (const int*)d_in[0];  const int* sl = (const int*)d_in[1];
    const int* tc = (const int*)d_in[2];
    const float* ce = (const float*)d_in[3];  const float* le = (const float*)d_in[4];
    const float* fcW = (const float*)d_in[5]; const float* fcb = (const float*)d_in[6];
    const float* eWi = (const float*)d_in[7]; const float* eWh = (const float*)d_in[8];
    const float* ebi = (const float*)d_in[9]; const float* ebh = (const float*)d_in[10];
    const float* dWi = (const float*)d_in[11]; const float* dWh = (const float*)d_in[12];
    const float* dbi = (const float*)d_in[13]; const float* dbh = (const float*)d_in[14];
    const float* Wq = (const float*)d_in[15]; const float* Wk = (const float*)d_in[16];
    const float* Wcs = (const float*)d_in[17];
    const float* W1 = (const float*)d_in[18]; const float* b1 = (const float*)d_in[19];
    const float* W2 = (const float*)d_in[20]; const float* b2 = (const float*)d_in[21];
    const float* W3 = (const float*)d_in[22];
    float* out = (float*)d_out;
    float *Xs = sym(g_Xs), *Xt = sym(g_Xt), *enc = sym(g_enc), *tem = sym(g_tem),
          *gie = sym(g_gie), *gid = sym(g_gid), *es = sym(g_es), *av = sym(g_av), *st = sym(g_st);
    __nv_bfloat16 *es16 = (__nv_bfloat16*)sym(g_es16), *av16 = (__nv_bfloat16*)sym(g_av16);

    // launches 0-4, then enc_pk is launch #5 (ncu -s 5 -c 1 captures it)
    gather_k<<<(B_*S_*1024)/256, 256>>>(sc, sl, ce, le, Xs, B_*S_);          // 0
    gather_k<<<(B_*T_*1024)/256, 256>>>(tc, 0, ce, le, Xt, B_*T_);           // 1
    startemb_k<<<64, 256>>>(ce, le, fcW, fcb, st);                           // 2
    gemm_nt<<<dim3(4, B_*S_/128), 256>>>(Xs, 1024, fcW, 1024, fcb, enc, 512, 1024, 0);   // 3
    gemm_nt<<<dim3(H3/128, B_*S_/128), 256>>>(enc, 512, eWi, 512, ebi, gie, H3, 512, 0); // 4
    enc_pk<<<GRID, NTHR>>>(eWh, ebh);                                        // 5 <- profiled
    gemm_nt<<<dim3(4, B_*T_/128), 256>>>(Xt, 1024, fcW, 1024, fcb, tem, 512, 1024, 0);
    gemm_nt<<<dim3(H3/128, B_*T_/128), 256>>>(tem, 512, dWi, 1536, dbi, gid, H3, 512, 0);
    gemm_nt<<<dim3(H_/128, B_*S_/128), 256>>>(enc, 512, Wcs, 512, 0, av, H_, 512, 0);
    gemm_nt<<<dim3(H_/128, B_*S_/128), 256>>>(es, H_, Wk, H_, 0, av, H_, 1024, 1);
    tobf16_k<<<(int)(((long)B_*S_*H_ + 255)/256), 256>>>(es, es16, (long)B_*S_*H_);
    tobf16_k<<<(int)(((long)B_*S_*H_ + 255)/256), 256>>>(av, av16, (long)B_*S_*H_);
    dec_pk<<<GRID, NTHR>>>(dWi, dWh, dbi, dbh, Wq, W1, b1, W2, b2, W3, out);
}

// round 11
// speedup vs baseline: 1.2313x; 1.0497x over previous
#include <cuda_runtime.h>
#include <cuda_bf16.h>
#include <math.h>

#define B_ 32
#define S_ 512
#define T_ 128
#define H_ 1024
#define H3 3072
#define F2 4096
#define FF 2048
#define V_ 128
#define GRID 144
#define NTHR 256

__device__ float g_Xs[B_*S_*1024];
__device__ float g_Xt[B_*T_*1024];
__device__ float g_enc[B_*S_*512];
__device__ float g_tem[B_*T_*512];
__device__ float g_gie[(size_t)B_*S_*H3];
__device__ float g_gid[(size_t)B_*T_*H3];
__device__ float g_es[(size_t)B_*S_*H_];
__device__ float g_av[(size_t)B_*S_*H_];
__device__ __nv_bfloat16 g_es16[(size_t)B_*S_*H_];
__device__ __nv_bfloat16 g_av16[(size_t)B_*S_*H_];
__device__ float g_h[B_*H_];
__device__ float g_hd[B_*H_];
__device__ float g_ctA[B_*H_], g_ctB[B_*H_];
__device__ float g_ghp[6*B_*H3];
__device__ float g_cip[6*B_*H3];
__device__ float g_y1p[4*B_*F2];
__device__ float g_y2p[16*B_*FF];
__device__ float g_qp[4*B_*H_];
__device__ float g_sp[8*B_*V_];
__device__ float g_att[B_*S_];
__device__ float g_st[512];
__device__ float g_xc[B_*1536];
__device__ unsigned g_cnt;
__device__ volatile unsigned g_gen;

__device__ __forceinline__ void gsync() {
    __syncthreads();
    if (threadIdx.x == 0) {
        __threadfence();
        unsigned gen = g_gen;
        if (atomicAdd(&g_cnt, 1u) == GRID - 1u) {
            g_cnt = 0;
            __threadfence();
            g_gen = gen + 1;
        } else {
            while (g_gen == gen) __nanosleep(64);
        }
        __threadfence();
    }
    __syncthreads();
}

__device__ __forceinline__ float4 loadA(const float* A0, const float* A1, int astr,
    const float* AP, long sstr, int P, const float* ab, int rl, int apN, int ar, int ko)
{
    float4 v;
    if (AP) {
        v = make_float4(0.f, 0.f, 0.f, 0.f);
        for (int p = 0; p < P; p++) {
            float4 u = *(const float4*)&AP[(long)p * sstr + (long)ar * apN + ko];
            v.x += u.x; v.y += u.y; v.z += u.z; v.w += u.w;
        }
        if (ab) { float4 u = *(const float4*)&ab[ko]; v.x += u.x; v.y += u.y; v.z += u.z; v.w += u.w; }
        if (rl) { v.x = fmaxf(v.x, 0.f); v.y = fmaxf(v.y, 0.f); v.z = fmaxf(v.z, 0.f); v.w = fmaxf(v.w, 0.f); }
    } else {
        v = *(const float4*)&A0[(long)ar * astr + ko];
        if (A1) { float4 u = *(const float4*)&A1[(long)ar * astr + ko]; v.x += u.x; v.y += u.y; v.z += u.z; v.w += u.w; }
    }
    return v;
}

// R8 compute structure + register prefetch of next chunk (hides gmem latency at occ=1).
__device__ __noinline__ void sgemm(float* SP,
    const float* A0, const float* A1, int astr,
    const float* AP, long sstr, int P, const float* ab, int rl, int apN,
    const float* W, int ldw, int n0, int k0, int klen, float* C, int cN)
{
    float* As = SP;            // [32k][36]
    float* Ws = SP + 1152;     // [32k][132]
    int tid = threadIdx.x, bq = tid >> 5, nq = tid & 31;
    int ar = tid >> 3, kq = (tid & 7) * 4;
    float ac[4][4] = {};
    float4 wpre[4], apre;

    apre = loadA(A0, A1, astr, AP, sstr, P, ab, rl, apN, ar, k0 + kq);
#pragma unroll
    for (int it = 0; it < 4; it++)
        wpre[it] = *(const float4*)&W[(long)(n0 + nq + it*32) * ldw + k0 + bq * 4];

    for (int kk = k0; kk < k0 + klen; kk += 32) {
        __syncthreads();
        {
            int kb = (kq);
            As[(kb+0)*36+ar] = apre.x; As[(kb+1)*36+ar] = apre.y;
            As[(kb+2)*36+ar] = apre.z; As[(kb+3)*36+ar] = apre.w;
        }
#pragma unroll
        for (int it = 0; it < 4; it++) {
            int r = nq + it * 32;
            Ws[(bq*4+0)*132+r] = wpre[it].x; Ws[(bq*4+1)*132+r] = wpre[it].y;
            Ws[(bq*4+2)*132+r] = wpre[it].z; Ws[(bq*4+3)*132+r] = wpre[it].w;
        }
        __syncthreads();
        int kn = kk + 32;
        if (kn < k0 + klen) {
            apre = loadA(A0, A1, astr, AP, sstr, P, ab, rl, apN, ar, kn + kq);
#pragma unroll
            for (int it = 0; it < 4; it++)
                wpre[it] = *(const float4*)&W[(long)(n0 + nq + it*32) * ldw + kn + bq * 4];
        }
#pragma unroll
        for (int k = 0; k < 32; k++) {
            float4 a = *(const float4*)&As[k*36 + bq*4];
            float4 w = *(const float4*)&Ws[k*132 + nq*4];
            float avv[4] = {a.x, a.y, a.z, a.w}, wv[4] = {w.x, w.y, w.z, w.w};
#pragma unroll
            for (int i = 0; i < 4; i++)
#pragma unroll
                for (int j = 0; j < 4; j++) ac[i][j] = fmaf(avv[i], wv[j], ac[i][j]);
        }
    }
#pragma unroll
    for (int i = 0; i < 4; i++)
        *(float4*)&C[(long)(bq*4+i)*cN + n0 + nq*4] = *(float4*)ac[i];
}

__global__ void gather_k(const int* __restrict__ ch, const int* __restrict__ lg,
                         const float* __restrict__ ce, const float* __restrict__ le,
                         float* __restrict__ X, int ntok) {
    long i = (long)blockIdx.x * 256 + threadIdx.x;
    if (i >= (long)ntok * 1024) return;
    int tok = (int)(i >> 10), c = (int)(i & 1023);
    X[i] = (c < 512) ? ce[ch[tok] * 512 + c] : le[(lg ? lg[tok] : 4) * 512 + (c - 512)];
}

__global__ void startemb_k(const float* __restrict__ ce, const float* __restrict__ le,
                           const float* __restrict__ fcW, const float* __restrict__ fcb,
                           float* __restrict__ o) {
    int g = blockIdx.x * 8 + (threadIdx.x >> 5), l = threadIdx.x & 31;
    float a = 0.f;
    for (int k = l; k < 1024; k += 32)
        a += ((k < 512) ? ce[512 + k] : le[2048 + (k - 512)]) * fcW[g * 1024 + k];
#pragma unroll
    for (int s = 16; s; s >>= 1) a += __shfl_down_sync(~0u, a, s);
    if (!l) o[g] = a + fcb[g];
}

__global__ void tobf16_k(const float* __restrict__ src, __nv_bfloat16* __restrict__ dst, long n) {
    long i = (long)blockIdx.x * 256 + threadIdx.x;
    if (i < n) dst[i] = __float2bfloat16(src[i]);
}

__global__ void gemm_nt(const float* __restrict__ A, int lda,
                        const float* __restrict__ W, int ldw,
                        const float* __restrict__ bias,
                        float* __restrict__ C, int ldc, int K, int accf) {
    __shared__ float As[8][128], Ws[8][128];
    int bm = blockIdx.y * 128, bn = blockIdx.x * 128, tid = threadIdx.x;
    int lr = tid >> 1, lc = (tid & 1) * 4, tx = tid & 15, ty = tid >> 4;
    float acc[8][8] = {};
    for (int k0 = 0; k0 < K; k0 += 8) {
        float4 a = *(const float4*)&A[(long)(bm + lr) * lda + k0 + lc];
        float4 w = *(const float4*)&W[(long)(bn + lr) * ldw + k0 + lc];
        As[lc][lr] = a.x; As[lc+1][lr] = a.y; As[lc+2][lr] = a.z; As[lc+3][lr] = a.w;
        Ws[lc][lr] = w.x; Ws[lc+1][lr] = w.y; Ws[lc+2][lr] = w.z; Ws[lc+3][lr] = w.w;
        __syncthreads();
#pragma unroll
        for (int k = 0; k < 8; k++) {
            float avv[8], bv[8];
            *(float4*)avv = *(const float4*)&As[k][ty*8]; *(float4*)(avv+4) = *(const float4*)&As[k][ty*8+4];
            *(float4*)bv = *(const float4*)&Ws[k][tx*8]; *(float4*)(bv+4) = *(const float4*)&Ws[k][tx*8+4];
#pragma unroll
            for (int i = 0; i < 8; i++)
#pragma unroll
                for (int j = 0; j < 8; j++) acc[i][j] = fmaf(avv[i], bv[j], acc[i][j]);
        }
        __syncthreads();
    }
#pragma unroll
    for (int i = 0; i < 8; i++) {
        long row = bm + ty * 8 + i;
#pragma unroll
        for (int j = 0; j < 8; j += 4) {
            int col = bn + tx * 8 + j;
            float4 v = make_float4(acc[i][j], acc[i][j+1], acc[i][j+2], acc[i][j+3]);
            if (bias) { v.x += bias[col]; v.y += bias[col+1]; v.z += bias[col+2]; v.w += bias[col+3]; }
            float4* cp = (float4*)&C[row * ldc + col];
            if (accf) { float4 o = *cp; v.x += o.x; v.y += o.y; v.z += o.z; v.w += o.w; }
            *cp = v;
        }
    }
}

__global__ void __launch_bounds__(NTHR, 1) enc_pk(const float* __restrict__ Wh,
                                                  const float* __restrict__ bh) {
    __shared__ float SP[5664];
    int bid = blockIdx.x, tid = threadIdx.x;
    for (int i = bid * NTHR + tid; i < B_ * H_; i += GRID * NTHR) g_h[i] = 0.f;
    gsync();
    const int kb[7] = {0, 192, 384, 544, 704, 864, 1024};
    int nt = bid / 6, ks = bid % 6;
    for (int t = 0; t < S_; t++) {
        sgemm(SP, g_h, 0, H_, 0, 0, 0, 0, 0, 0, Wh, H_, nt * 128, kb[ks], kb[ks+1] - kb[ks],
              g_ghp + (long)ks * B_ * H3, H3);
        gsync();
        for (int i = bid * NTHR + tid; i < B_ * H_; i += GRID * NTHR) {
            int b = i >> 10, j = i & 1023;
            const float* gi = &g_gie[((size_t)(b * S_ + t)) * H3];
            float ir = gi[j], iz = gi[j + H_], in = gi[j + 2*H_];
            float hr = bh[j], hz = bh[j + H_], hn = bh[j + 2*H_];
            for (int p = 0; p < 6; p++) {
                const float* gp = &g_ghp[(long)p * B_ * H3 + (long)b * H3];
                hr += gp[j]; hz += gp[j + H_]; hn += gp[j + 2*H_];
            }
            float ho = g_h[i];
            float r = 1.f / (1.f + expf(-(ir + hr)));
            float z = 1.f / (1.f + expf(-(iz + hz)));
            float n = tanhf(in + r * hn);
            float hv = (1.f - z) * n + z * ho;
            g_h[i] = hv;
            g_es[((size_t)(b * S_ + t)) * H_ + j] = hv;
        }
        gsync();
    }
}

__global__ void __launch_bounds__(NTHR, 1) dec_pk(
    const float* __restrict__ Wi, const float* __restrict__ Wh,
    const float* __restrict__ bi, const float* __restrict__ bh,
    const float* __restrict__ Wq, const float* __restrict__ W1, const float* __restrict__ b1,
    const float* __restrict__ W2, const float* __restrict__ b2, const float* __restrict__ W3,
    float* __restrict__ out) {
    __shared__ float SP[5664];
    int bid = blockIdx.x, tid = threadIdx.x;
    for (int i = bid * NTHR + tid; i < B_ * 1536; i += GRID * NTHR) {
        int b = i / 1536, k = i % 1536;
        float v = (k < 512) ? g_st[k] : g_es[((size_t)(b * S_ + S_ - 1)) * H_ + k - 512];
        if (k >= 512) g_ctA[b * H_ + k - 512] = v;
        g_xc[i] = v;
    }
    gsync();
    { int nt = bid / 6, ks = bid % 6;
      sgemm(SP, g_xc, 0, 1536, 0, 0, 0, 0, 0, 0, Wi, 1536, nt * 128, ks * 256, 256,
            g_cip + (long)ks * B_ * H3, H3); }
    gsync();
    for (int i = bid * NTHR + tid; i < B_ * H_; i += GRID * NTHR) {
        int b = i >> 10, j = i & 1023;
        float ir = bi[j], iz = bi[j + H_], in = bi[j + 2*H_];
        for (int p = 0; p < 6; p++) {
            const float* gp = &g_cip[(long)p * B_ * H3 + (long)b * H3];
            ir += gp[j]; iz += gp[j + H_]; in += gp[j + 2*H_];
        }
        float hr = bh[j], hz = bh[j + H_], hn = bh[j + 2*H_];
        float r = 1.f / (1.f + expf(-(ir + hr)));
        float z = 1.f / (1.f + expf(-(iz + hz)));
        float n = tanhf(in + r * hn);
        g_hd[i] = (1.f - z) * n;
    }
    gsync();
    for (int t = 0; t < T_; t++) {
        const float* cp = (t & 1) ? g_ctB : g_ctA;
        float* cn = (t & 1) ? g_ctA : g_ctB;
        for (int it = bid; it < 256; it += GRID) {           // S1: y1p, qp, ghp
            if (it < 128) { int nt = it >> 2, ks = it & 3;
                sgemm(SP, g_hd, cp, H_, 0,0,0,0,0,0, W1, H_, nt*128, ks*256, 256, g_y1p + (long)ks*B_*F2, F2); }
            else if (it < 160) { int i2 = it - 128, nt = i2 >> 2, ks = i2 & 3;
                sgemm(SP, g_hd, 0, H_, 0,0,0,0,0,0, Wq, H_, nt*128, ks*256, 256, g_qp + (long)ks*B_*H_, H_); }
            else { int i2 = it - 160, nt = i2 >> 2, ks = i2 & 3;
                sgemm(SP, g_hd, 0, H_, 0,0,0,0,0,0, Wh, H_, nt*128, ks*256, 256, g_ghp + (long)ks*B_*H3, H3); }
        }
        gsync();
        for (int it = bid; it < 288; it += GRID) {           // S2: y2p + att logits
            if (it < 256) { int nt = it >> 4, ks = it & 15;
                sgemm(SP, 0,0,0, g_y1p, (long)B_*F2, 4, b1, 1, F2, W2, F2, nt*128, ks*256, 256,
                      g_y2p + (long)ks*B_*FF, FF); }
            else {
                int b = it - 256;
                float* q = SP;
                __syncthreads();
                for (int i = tid; i < H_; i += NTHR) {
                    float s = 0.f;
                    for (int p = 0; p < 4; p++) s += g_qp[(long)p*B_*H_ + b*H_ + i];
                    q[i] = s;
                }
                __syncthreads();
                int w = tid >> 5, l = tid & 31;
                for (int s = w; s < S_; s += 8) {
                    const __nv_bfloat16* e = &g_es16[((size_t)(b * S_ + s)) * H_];
                    float a = 0.f;
#pragma unroll
                    for (int m = 0; m < 4; m++) {
                        const __nv_bfloat162* e2 = (const __nv_bfloat162*)&e[m*256 + l*8];
                        const float* qq = &q[m*256 + l*8];
#pragma unroll
                        for (int u = 0; u < 4; u++) {
                            float2 p = __bfloat1622float2(e2[u]);
                            a += p.x * qq[u*2] + p.y * qq[u*2+1];
                        }
                    }
#pragma unroll
                    for (int o = 16; o; o >>= 1) a += __shfl_down_sync(~0u, a, o);
                    if (!l) g_att[b * S_ + s] = a;
                }
                __syncthreads();
            }
        }
        gsync();
        for (int it = bid; it < 136; it += GRID) {           // S3: softmax+ctx + sp
            if (it < 128) {
                int b = it >> 2, hq = it & 3;
                float* red = SP + 512;
                __syncthreads();
                float v0 = g_att[b*S_ + tid], v1 = g_att[b*S_ + 256 + tid];
                red[tid] = fmaxf(v0, v1); __syncthreads();
                for (int s = 128; s; s >>= 1) { if (tid < s) red[tid] = fmaxf(red[tid], red[tid+s]); __syncthreads(); }
                float mx = red[0]; __syncthreads();
                float e0 = expf(v0 - mx), e1 = expf(v1 - mx);
                red[tid] = e0 + e1; __syncthreads();
                for (int s = 128; s; s >>= 1) { if (tid < s) red[tid] += red[tid+s]; __syncthreads(); }
                float inv = 1.f / red[0]; __syncthreads();
                SP[tid] = e0 * inv; SP[tid + 256] = e1 * inv;
                __syncthreads();
                int hc = hq * 256 + tid;
                const __nv_bfloat16* a = &g_av16[((size_t)b * S_) * H_ + hc];
                float acc = 0.f;
#pragma unroll 8
                for (int s = 0; s < S_; s++) acc += SP[s] * __bfloat162float(a[(size_t)s * H_]);
                cn[b * H_ + hc] = acc;
                __syncthreads();
            } else { int ks = it - 128;
                sgemm(SP, 0,0,0, g_y2p, (long)B_*FF, 16, b2, 1, FF, W3, FF, 0, ks*256, 256,
                      g_sp + (long)ks*B_*V_, V_); }
        }
        gsync();
        for (int it = bid; it < 96; it += GRID) {            // S4: cip (ctx GEMM)
            int nt = it >> 2, ks = it & 3;
            sgemm(SP, cn, 0, H_, 0,0,0,0,0,0, Wi + 512, 1536, nt*128, ks*256, 256,
                  g_cip + (long)ks*B_*H3, H3);
        }
        gsync();
        for (int i = bid * NTHR + tid; i < B_ * H_; i += GRID * NTHR) {   // S5: gates
            int b = i >> 10, j = i & 1023;
            const float* gi = &g_gid[((size_t)(b * T_ + t)) * H3];
            float ir = gi[j], iz = gi[j + H_], in = gi[j + 2*H_];
            for (int p = 0; p < 4; p++) {
                const float* gp = &g_cip[(long)p*B_*H3 + (long)b*H3];
                ir += gp[j]; iz += gp[j + H_]; in += gp[j + 2*H_];
            }
            float hr = bh[j], hz = bh[j + H_], hn = bh[j + 2*H_];
            for (int p = 0; p < 4; p++) {
                const float* gp = &g_ghp[(long)p*B_*H3 + (long)b*H3];
                hr += gp[j]; hz += gp[j + H_]; hn += gp[j + 2*H_];
            }
            float ho = g_hd[i];
            float r = 1.f / (1.f + expf(-(ir + hr)));
            float z = 1.f / (1.f + expf(-(iz + hz)));
            float n = tanhf(in + r * hn);
            g_hd[i] = (1.f - z) * n + z * ho;
        }
        for (int i = bid * NTHR + tid; i < B_ * V_; i += GRID * NTHR) {
            int b = i >> 7, v = i & 127;
            float s = 0.f;
            for (int p = 0; p < 8; p++) s += g_sp[p*B_*V_ + b*V_ + v];
            out[((size_t)(b * T_ + t)) * V_ + v] = s;
        }
        gsync();
    }
}

static float* sym(const void* s) { void* p = 0; cudaGetSymbolAddress(&p, s); return (float*)p; }

extern "C" void kernel_launch(void* const* d_in, const int*, int, void* d_out, int) {
    const int* sc = (const int*)d_in[0];  const int* sl = (const int*)d_in[1];
    const int* tc = (const int*)d_in[2];
    const float* ce = (const float*)d_in[3];  const float* le = (const float*)d_in[4];
    const float* fcW = (const float*)d_in[5]; const float* fcb = (const float*)d_in[6];
    const float* eWi = (const float*)d_in[7]; const float* eWh = (const float*)d_in[8];
    const float* ebi = (const float*)d_in[9]; const float* ebh = (const float*)d_in[10];
    const float* dWi = (const float*)d_in[11]; const float* dWh = (const float*)d_in[12];
    const float* dbi = (const float*)d_in[13]; const float* dbh = (const float*)d_in[14];
    const float* Wq = (const float*)d_in[15]; const float* Wk = (const float*)d_in[16];
    const float* Wcs = (const float*)d_in[17];
    const float* W1 = (const float*)d_in[18]; const float* b1 = (const float*)d_in[19];
    const float* W2 = (const float*)d_in[20]; const float* b2 = (const float*)d_in[21];
    const float* W3 = (const float*)d_in[22];
    float* out = (float*)d_out;
    float *Xs = sym(g_Xs), *Xt = sym(g_Xt), *enc = sym(g_enc), *tem = sym(g_tem),
          *gie = sym(g_gie), *gid = sym(g_gid), *es = sym(g_es), *av = sym(g_av), *st = sym(g_st);
    __nv_bfloat16 *es16 = (__nv_bfloat16*)sym(g_es16), *av16 = (__nv_bfloat16*)sym(g_av16);

    gather_k<<<(B_*S_*1024)/256, 256>>>(sc, sl, ce, le, Xs, B_*S_);
    gather_k<<<(B_*T_*1024)/256, 256>>>(tc, 0, ce, le, Xt, B_*T_);
    startemb_k<<<64, 256>>>(ce, le, fcW, fcb, st);
    gemm_nt<<<dim3(4, B_*S_/128), 256>>>(Xs, 1024, fcW, 1024, fcb, enc, 512, 1024, 0);
    gemm_nt<<<dim3(H3/128, B_*S_/128), 256>>>(enc, 512, eWi, 512, ebi, gie, H3, 512, 0);
    enc_pk<<<GRID, NTHR>>>(eWh, ebh);
    gemm_nt<<<dim3(4, B_*T_/128), 256>>>(Xt, 1024, fcW, 1024, fcb, tem, 512, 1024, 0);
    gemm_nt<<<dim3(H3/128, B_*T_/128), 256>>>(tem, 512, dWi, 1536, dbi, gid, H3, 512, 0);
    gemm_nt<<<dim3(H_/128, B_*S_/128), 256>>>(enc, 512, Wcs, 512, 0, av, H_, 512, 0);
    gemm_nt<<<dim3(H_/128, B_*S_/128), 256>>>(es, H_, Wk, H_, 0, av, H_, 1024, 1);
    tobf16_k<<<(int)(((long)B_*S_*H_ + 255)/256), 256>>>(es, es16, (long)B_*S_*H_);
    tobf16_k<<<(int)(((long)B_*S_*H_ + 255)/256), 256>>>(av, av16, (long)B_*S_*H_);
    dec_pk<<<GRID, NTHR>>>(dWi, dWh, dbi, dbh, Wq, W1, b1, W2, b2, W3, out);
}

// round 12
// speedup vs baseline: 1.3048x; 1.0597x over previous
#include <cuda_runtime.h>
#include <cuda_bf16.h>
#include <math.h>

#define B_ 32
#define S_ 512
#define T_ 128
#define H_ 1024
#define H3 3072
#define F2 4096
#define FF 2048
#define V_ 128
#define GRID 288
#define NTHR 256

__device__ float g_Xs[B_*S_*1024];
__device__ float g_Xt[B_*T_*1024];
__device__ float g_enc[B_*S_*512];
__device__ float g_tem[B_*T_*512];
__device__ float g_gie[(size_t)B_*S_*H3];
__device__ float g_gid[(size_t)B_*T_*H3];
__device__ float g_es[(size_t)B_*S_*H_];
__device__ float g_av[(size_t)B_*S_*H_];
__device__ __nv_bfloat16 g_es16[(size_t)B_*S_*H_];
__device__ __nv_bfloat16 g_av16[(size_t)B_*S_*H_];
__device__ float g_h[B_*H_];
__device__ float g_hd[B_*H_];
__device__ float g_ctA[B_*H_], g_ctB[B_*H_];
__device__ float g_ghp[12*B_*H3];
__device__ float g_cip[12*B_*H3];
__device__ float g_y1p[4*B_*F2];
__device__ float g_y2p[16*B_*FF];
__device__ float g_qp[4*B_*H_];
__device__ float g_sp[16*B_*V_];
__device__ float g_att[B_*S_];
__device__ float g_st[512];
__device__ float g_xc[B_*1536];
__device__ unsigned g_cnt;
__device__ volatile unsigned g_gen;

__device__ __forceinline__ void gsync() {
    __syncthreads();
    if (threadIdx.x == 0) {
        __threadfence();
        unsigned gen = g_gen;
        if (atomicAdd(&g_cnt, 1u) == GRID - 1u) {
            g_cnt = 0;
            __threadfence();
            g_gen = gen + 1;
        } else {
            while (g_gen == gen) __nanosleep(64);
        }
        __threadfence();
    }
    __syncthreads();
}

__device__ __forceinline__ float4 loadA(const float* A0, const float* A1, int astr,
    const float* AP, long sstr, int P, const float* ab, int rl, int apN, int ar, int ko)
{
    float4 v;
    if (AP) {
        v = make_float4(0.f, 0.f, 0.f, 0.f);
        for (int p = 0; p < P; p++) {
            float4 u = *(const float4*)&AP[(long)p * sstr + (long)ar * apN + ko];
            v.x += u.x; v.y += u.y; v.z += u.z; v.w += u.w;
        }
        if (ab) { float4 u = *(const float4*)&ab[ko]; v.x += u.x; v.y += u.y; v.z += u.z; v.w += u.w; }
        if (rl) { v.x = fmaxf(v.x, 0.f); v.y = fmaxf(v.y, 0.f); v.z = fmaxf(v.z, 0.f); v.w = fmaxf(v.w, 0.f); }
    } else {
        v = *(const float4*)&A0[(long)ar * astr + ko];
        if (A1) { float4 u = *(const float4*)&A1[(long)ar * astr + ko]; v.x += u.x; v.y += u.y; v.z += u.z; v.w += u.w; }
    }
    return v;
}

// R11 structure + FFMA2 (fma.rn.f32x2) inner loop: pairs along b (natural in As float4).
__device__ __noinline__ void sgemm(float* SP,
    const float* A0, const float* A1, int astr,
    const float* AP, long sstr, int P, const float* ab, int rl, int apN,
    const float* W, int ldw, int n0, int k0, int klen, float* C, int cN)
{
    float* As = SP;            // [32k][36]
    float* Ws = SP + 1152;     // [32k][132]
    int tid = threadIdx.x, bq = tid >> 5, nq = tid & 31;
    int ar = tid >> 3, kq = (tid & 7) * 4;
    unsigned long long acc2[2][4] = {};
    float4 wpre[4], apre;

    apre = loadA(A0, A1, astr, AP, sstr, P, ab, rl, apN, ar, k0 + kq);
#pragma unroll
    for (int it = 0; it < 4; it++)
        wpre[it] = *(const float4*)&W[(long)(n0 + nq + it*32) * ldw + k0 + bq * 4];

    for (int kk = k0; kk < k0 + klen; kk += 32) {
        __syncthreads();
        As[(kq+0)*36+ar] = apre.x; As[(kq+1)*36+ar] = apre.y;
        As[(kq+2)*36+ar] = apre.z; As[(kq+3)*36+ar] = apre.w;
#pragma unroll
        for (int it = 0; it < 4; it++) {
            int r = nq + it * 32;
            Ws[(bq*4+0)*132+r] = wpre[it].x; Ws[(bq*4+1)*132+r] = wpre[it].y;
            Ws[(bq*4+2)*132+r] = wpre[it].z; Ws[(bq*4+3)*132+r] = wpre[it].w;
        }
        __syncthreads();
        int kn = kk + 32;
        if (kn < k0 + klen) {
            apre = loadA(A0, A1, astr, AP, sstr, P, ab, rl, apN, ar, kn + kq);
#pragma unroll
            for (int it = 0; it < 4; it++)
                wpre[it] = *(const float4*)&W[(long)(n0 + nq + it*32) * ldw + kn + bq * 4];
        }
#pragma unroll
        for (int k = 0; k < 32; k++) {
            ulonglong2 ap = *(const ulonglong2*)&As[k*36 + bq*4];   // (b0,b1),(b2,b3)
            float4 w = *(const float4*)&Ws[k*132 + nq*4];
            unsigned long long wp0, wp1, wp2, wp3;
            asm("mov.b64 %0,{%1,%1};" : "=l"(wp0) : "r"(__float_as_uint(w.x)));
            asm("mov.b64 %0,{%1,%1};" : "=l"(wp1) : "r"(__float_as_uint(w.y)));
            asm("mov.b64 %0,{%1,%1};" : "=l"(wp2) : "r"(__float_as_uint(w.z)));
            asm("mov.b64 %0,{%1,%1};" : "=l"(wp3) : "r"(__float_as_uint(w.w)));
            asm("fma.rn.f32x2 %0,%1,%2,%0;" : "+l"(acc2[0][0]) : "l"(ap.x), "l"(wp0));
            asm("fma.rn.f32x2 %0,%1,%2,%0;" : "+l"(acc2[0][1]) : "l"(ap.x), "l"(wp1));
            asm("fma.rn.f32x2 %0,%1,%2,%0;" : "+l"(acc2[0][2]) : "l"(ap.x), "l"(wp2));
            asm("fma.rn.f32x2 %0,%1,%2,%0;" : "+l"(acc2[0][3]) : "l"(ap.x), "l"(wp3));
            asm("fma.rn.f32x2 %0,%1,%2,%0;" : "+l"(acc2[1][0]) : "l"(ap.y), "l"(wp0));
            asm("fma.rn.f32x2 %0,%1,%2,%0;" : "+l"(acc2[1][1]) : "l"(ap.y), "l"(wp1));
            asm("fma.rn.f32x2 %0,%1,%2,%0;" : "+l"(acc2[1][2]) : "l"(ap.y), "l"(wp2));
            asm("fma.rn.f32x2 %0,%1,%2,%0;" : "+l"(acc2[1][3]) : "l"(ap.y), "l"(wp3));
        }
    }
    float ac[4][4];
#pragma unroll
    for (int p = 0; p < 2; p++)
#pragma unroll
        for (int j = 0; j < 4; j++) {
            float lo, hi;
            asm("mov.b64 {%0,%1},%2;" : "=f"(lo), "=f"(hi) : "l"(acc2[p][j]));
            ac[2*p][j] = lo; ac[2*p+1][j] = hi;
        }
#pragma unroll
    for (int i = 0; i < 4; i++)
        *(float4*)&C[(long)(bq*4+i)*cN + n0 + nq*4] = *(float4*)ac[i];
}

__global__ void gather_k(const int* __restrict__ ch, const int* __restrict__ lg,
                         const float* __restrict__ ce, const float* __restrict__ le,
                         float* __restrict__ X, int ntok) {
    long i = (long)blockIdx.x * 256 + threadIdx.x;
    if (i >= (long)ntok * 1024) return;
    int tok = (int)(i >> 10), c = (int)(i & 1023);
    X[i] = (c < 512) ? ce[ch[tok] * 512 + c] : le[(lg ? lg[tok] : 4) * 512 + (c - 512)];
}

__global__ void startemb_k(const float* __restrict__ ce, const float* __restrict__ le,
                           const float* __restrict__ fcW, const float* __restrict__ fcb,
                           float* __restrict__ o) {
    int g = blockIdx.x * 8 + (threadIdx.x >> 5), l = threadIdx.x & 31;
    float a = 0.f;
    for (int k = l; k < 1024; k += 32)
        a += ((k < 512) ? ce[512 + k] : le[2048 + (k - 512)]) * fcW[g * 1024 + k];
#pragma unroll
    for (int s = 16; s; s >>= 1) a += __shfl_down_sync(~0u, a, s);
    if (!l) o[g] = a + fcb[g];
}

__global__ void tobf16_k(const float* __restrict__ src, __nv_bfloat16* __restrict__ dst, long n) {
    long i = (long)blockIdx.x * 256 + threadIdx.x;
    if (i < n) dst[i] = __float2bfloat16(src[i]);
}

__global__ void gemm_nt(const float* __restrict__ A, int lda,
                        const float* __restrict__ W, int ldw,
                        const float* __restrict__ bias,
                        float* __restrict__ C, int ldc, int K, int accf) {
    __shared__ float As[8][128], Ws[8][128];
    int bm = blockIdx.y * 128, bn = blockIdx.x * 128, tid = threadIdx.x;
    int lr = tid >> 1, lc = (tid & 1) * 4, tx = tid & 15, ty = tid >> 4;
    float acc[8][8] = {};
    for (int k0 = 0; k0 < K; k0 += 8) {
        float4 a = *(const float4*)&A[(long)(bm + lr) * lda + k0 + lc];
        float4 w = *(const float4*)&W[(long)(bn + lr) * ldw + k0 + lc];
        As[lc][lr] = a.x; As[lc+1][lr] = a.y; As[lc+2][lr] = a.z; As[lc+3][lr] = a.w;
        Ws[lc][lr] = w.x; Ws[lc+1][lr] = w.y; Ws[lc+2][lr] = w.z; Ws[lc+3][lr] = w.w;
        __syncthreads();
#pragma unroll
        for (int k = 0; k < 8; k++) {
            float avv[8], bv[8];
            *(float4*)avv = *(const float4*)&As[k][ty*8]; *(float4*)(avv+4) = *(const float4*)&As[k][ty*8+4];
            *(float4*)bv = *(const float4*)&Ws[k][tx*8]; *(float4*)(bv+4) = *(const float4*)&Ws[k][tx*8+4];
#pragma unroll
            for (int i = 0; i < 8; i++)
#pragma unroll
                for (int j = 0; j < 8; j++) acc[i][j] = fmaf(avv[i], bv[j], acc[i][j]);
        }
        __syncthreads();
    }
#pragma unroll
    for (int i = 0; i < 8; i++) {
        long row = bm + ty * 8 + i;
#pragma unroll
        for (int j = 0; j < 8; j += 4) {
            int col = bn + tx * 8 + j;
            float4 v = make_float4(acc[i][j], acc[i][j+1], acc[i][j+2], acc[i][j+3]);
            if (bias) { v.x += bias[col]; v.y += bias[col+1]; v.z += bias[col+2]; v.w += bias[col+3]; }
            float4* cp = (float4*)&C[row * ldc + col];
            if (accf) { float4 o = *cp; v.x += o.x; v.y += o.y; v.z += o.z; v.w += o.w; }
            *cp = v;
        }
    }
}

__global__ void __launch_bounds__(NTHR, 2) enc_pk(const float* __restrict__ Wh,
                                                  const float* __restrict__ bh) {
    __shared__ __align__(16) float SP[5664];
    int bid = blockIdx.x, tid = threadIdx.x;
    for (int i = bid * NTHR + tid; i < B_ * H_; i += GRID * NTHR) g_h[i] = 0.f;
    gsync();
    const int kb[13] = {0,96,192,288,384,480,576,672,768,832,896,960,1024};
    int nt = bid / 12, ks = bid % 12;
    for (int t = 0; t < S_; t++) {
        sgemm(SP, g_h, 0, H_, 0, 0, 0, 0, 0, 0, Wh, H_, nt * 128, kb[ks], kb[ks+1] - kb[ks],
              g_ghp + (long)ks * B_ * H3, H3);
        gsync();
        for (int i = bid * NTHR + tid; i < B_ * H_; i += GRID * NTHR) {
            int b = i >> 10, j = i & 1023;
            const float* gi = &g_gie[((size_t)(b * S_ + t)) * H3];
            float ir = gi[j], iz = gi[j + H_], in = gi[j + 2*H_];
            float hr = bh[j], hz = bh[j + H_], hn = bh[j + 2*H_];
            for (int p = 0; p < 12; p++) {
                const float* gp = &g_ghp[(long)p * B_ * H3 + (long)b * H3];
                hr += gp[j]; hz += gp[j + H_]; hn += gp[j + 2*H_];
            }
            float ho = g_h[i];
            float r = 1.f / (1.f + expf(-(ir + hr)));
            float z = 1.f / (1.f + expf(-(iz + hz)));
            float n = tanhf(in + r * hn);
            float hv = (1.f - z) * n + z * ho;
            g_h[i] = hv;
            g_es[((size_t)(b * S_ + t)) * H_ + j] = hv;
        }
        gsync();
    }
}

__global__ void __launch_bounds__(NTHR, 2) dec_pk(
    const float* __restrict__ Wi, const float* __restrict__ Wh,
    const float* __restrict__ bi, const float* __restrict__ bh,
    const float* __restrict__ Wq, const float* __restrict__ W1, const float* __restrict__ b1,
    const float* __restrict__ W2, const float* __restrict__ b2, const float* __restrict__ W3,
    float* __restrict__ out) {
    __shared__ __align__(16) float SP[5664];
    int bid = blockIdx.x, tid = threadIdx.x;
    for (int i = bid * NTHR + tid; i < B_ * 1536; i += GRID * NTHR) {
        int b = i / 1536, k = i % 1536;
        float v = (k < 512) ? g_st[k] : g_es[((size_t)(b * S_ + S_ - 1)) * H_ + k - 512];
        if (k >= 512) g_ctA[b * H_ + k - 512] = v;
        g_xc[i] = v;
    }
    gsync();
    { int nt = bid / 12, ks = bid % 12;
      sgemm(SP, g_xc, 0, 1536, 0, 0, 0, 0, 0, 0, Wi, 1536, nt * 128, ks * 128, 128,
            g_cip + (long)ks * B_ * H3, H3); }
    gsync();
    for (int i = bid * NTHR + tid; i < B_ * H_; i += GRID * NTHR) {
        int b = i >> 10, j = i & 1023;
        float ir = bi[j], iz = bi[j + H_], in = bi[j + 2*H_];
        for (int p = 0; p < 12; p++) {
            const float* gp = &g_cip[(long)p * B_ * H3 + (long)b * H3];
            ir += gp[j]; iz += gp[j + H_]; in += gp[j + 2*H_];
        }
        float hr = bh[j], hz = bh[j + H_], hn = bh[j + 2*H_];
        float r = 1.f / (1.f + expf(-(ir + hr)));
        float z = 1.f / (1.f + expf(-(iz + hz)));
        float n = tanhf(in + r * hn);
        g_hd[i] = (1.f - z) * n;
    }
    gsync();
    for (int t = 0; t < T_; t++) {
        const float* cp = (t & 1) ? g_ctB : g_ctA;
        float* cn = (t & 1) ? g_ctA : g_ctB;
        for (int it = bid; it < 256; it += GRID) {           // S1: y1p, qp, ghp (1 round)
            if (it < 128) { int nt = it >> 2, ks = it & 3;
                sgemm(SP, g_hd, cp, H_, 0,0,0,0,0,0, W1, H_, nt*128, ks*256, 256, g_y1p + (long)ks*B_*F2, F2); }
            else if (it < 160) { int i2 = it - 128, nt = i2 >> 2, ks = i2 & 3;
                sgemm(SP, g_hd, 0, H_, 0,0,0,0,0,0, Wq, H_, nt*128, ks*256, 256, g_qp + (long)ks*B_*H_, H_); }
            else { int i2 = it - 160, nt = i2 >> 2, ks = i2 & 3;
                sgemm(SP, g_hd, 0, H_, 0,0,0,0,0,0, Wh, H_, nt*128, ks*256, 256, g_ghp + (long)ks*B_*H3, H3); }
        }
        gsync();
        for (int it = bid; it < 288; it += GRID) {           // S2: y2p + att logits (1 round)
            if (it < 256) { int nt = it >> 4, ks = it & 15;
                sgemm(SP, 0,0,0, g_y1p, (long)B_*F2, 4, b1, 1, F2, W2, F2, nt*128, ks*256, 256,
                      g_y2p + (long)ks*B_*FF, FF); }
            else {
                int b = it - 256;
                float* q = SP;
                __syncthreads();
                for (int i = tid; i < H_; i += NTHR) {
                    float s = 0.f;
                    for (int p = 0; p < 4; p++) s += g_qp[(long)p*B_*H_ + b*H_ + i];
                    q[i] = s;
                }
                __syncthreads();
                int w = tid >> 5, l = tid & 31;
                for (int s = w; s < S_; s += 8) {
                    const __nv_bfloat16* e = &g_es16[((size_t)(b * S_ + s)) * H_];
                    float a = 0.f;
#pragma unroll
                    for (int m = 0; m < 4; m++) {
                        const __nv_bfloat162* e2 = (const __nv_bfloat162*)&e[m*256 + l*8];
                        const float* qq = &q[m*256 + l*8];
#pragma unroll
                        for (int u = 0; u < 4; u++) {
                            float2 p = __bfloat1622float2(e2[u]);
                            a += p.x * qq[u*2] + p.y * qq[u*2+1];
                        }
                    }
#pragma unroll
                    for (int o = 16; o; o >>= 1) a += __shfl_down_sync(~0u, a, o);
                    if (!l) g_att[b * S_ + s] = a;
                }
                __syncthreads();
            }
        }
        gsync();
        for (int it = bid; it < 144; it += GRID) {           // S3: softmax+ctx + sp (1 round)
            if (it < 128) {
                int b = it >> 2, hq = it & 3;
                float* red = SP + 512;
                __syncthreads();
                float v0 = g_att[b*S_ + tid], v1 = g_att[b*S_ + 256 + tid];
                red[tid] = fmaxf(v0, v1); __syncthreads();
                for (int s = 128; s; s >>= 1) { if (tid < s) red[tid] = fmaxf(red[tid], red[tid+s]); __syncthreads(); }
                float mx = red[0]; __syncthreads();
                float e0 = expf(v0 - mx), e1 = expf(v1 - mx);
                red[tid] = e0 + e1; __syncthreads();
                for (int s = 128; s; s >>= 1) { if (tid < s) red[tid] += red[tid+s]; __syncthreads(); }
                float inv = 1.f / red[0]; __syncthreads();
                SP[tid] = e0 * inv; SP[tid + 256] = e1 * inv;
                __syncthreads();
                int hc = hq * 256 + tid;
                const __nv_bfloat16* a = &g_av16[((size_t)b * S_) * H_ + hc];
                float acc = 0.f;
#pragma unroll 8
                for (int s = 0; s < S_; s++) acc += SP[s] * __bfloat162float(a[(size_t)s * H_]);
                cn[b * H_ + hc] = acc;
                __syncthreads();
            } else { int ks = it - 128;
                sgemm(SP, 0,0,0, g_y2p, (long)B_*FF, 16, b2, 1, FF, W3, FF, 0, ks*128, 128,
                      g_sp + (long)ks*B_*V_, V_); }
        }
        gsync();
        for (int it = bid; it < 192; it += GRID) {           // S4: cip (8-way K, 1 round)
            int nt = it >> 3, ks = it & 7;
            sgemm(SP, cn, 0, H_, 0,0,0,0,0,0, Wi + 512, 1536, nt*128, ks*128, 128,
                  g_cip + (long)ks*B_*H3, H3);
        }
        gsync();
        for (int i = bid * NTHR + tid; i < B_ * H_; i += GRID * NTHR) {   // S5: gates
            int b = i >> 10, j = i & 1023;
            const float* gi = &g_gid[((size_t)(b * T_ + t)) * H3];
            float ir = gi[j], iz = gi[j + H_], in = gi[j + 2*H_];
            for (int p = 0; p < 8; p++) {
                const float* gp = &g_cip[(long)p*B_*H3 + (long)b*H3];
                ir += gp[j]; iz += gp[j + H_]; in += gp[j + 2*H_];
            }
            float hr = bh[j], hz = bh[j + H_], hn = bh[j + 2*H_];
            for (int p = 0; p < 4; p++) {
                const float* gp = &g_ghp[(long)p*B_*H3 + (long)b*H3];
                hr += gp[j]; hz += gp[j + H_]; hn += gp[j + 2*H_];
            }
            float ho = g_hd[i];
            float r = 1.f / (1.f + expf(-(ir + hr)));
            float z = 1.f / (1.f + expf(-(iz + hz)));
            float n = tanhf(in + r * hn);
            g_hd[i] = (1.f - z) * n + z * ho;
        }
        for (int i = bid * NTHR + tid; i < B_ * V_; i += GRID * NTHR) {
            int b = i >> 7, v = i & 127;
            float s = 0.f;
            for (int p = 0; p < 16; p++) s += g_sp[p*B_*V_ + b*V_ + v];
            out[((size_t)(b * T_ + t)) * V_ + v] = s;
        }
        gsync();
    }
}

static float* sym(const void* s) { void* p = 0; cudaGetSymbolAddress(&p, s); return (float*)p; }

extern "C" void kernel_launch(void* const* d_in, const int*, int, void* d_out, int) {
    const int* sc = (const int*)d_in[0];  const int* sl = (const int*)d_in[1];
    const int* tc = (const int*)d_in[2];
    const float* ce = (const float*)d_in[3];  const float* le = (const float*)d_in[4];
    const float* fcW = (const float*)d_in[5]; const float* fcb = (const float*)d_in[6];
    const float* eWi = (const float*)d_in[7]; const float* eWh = (const float*)d_in[8];
    const float* ebi = (const float*)d_in[9]; const float* ebh = (const float*)d_in[10];
    const float* dWi = (const float*)d_in[11]; const float* dWh = (const float*)d_in[12];
    const float* dbi = (const float*)d_in[13]; const float* dbh = (const float*)d_in[14];
    const float* Wq = (const float*)d_in[15]; const float* Wk = (const float*)d_in[16];
    const float* Wcs = (const float*)d_in[17];
    const float* W1 = (const float*)d_in[18]; const float* b1 = (const float*)d_in[19];
    const float* W2 = (const float*)d_in[20]; const float* b2 = (const float*)d_in[21];
    const float* W3 = (const float*)d_in[22];
    float* out = (float*)d_out;
    float *Xs = sym(g_Xs), *Xt = sym(g_Xt), *enc = sym(g_enc), *tem = sym(g_tem),
          *gie = sym(g_gie), *gid = sym(g_gid), *es = sym(g_es), *av = sym(g_av), *st = sym(g_st);
    __nv_bfloat16 *es16 = (__nv_bfloat16*)sym(g_es16), *av16 = (__nv_bfloat16*)sym(g_av16);

    gather_k<<<(B_*S_*1024)/256, 256>>>(sc, sl, ce, le, Xs, B_*S_);                      // 0
    gemm_nt<<<dim3(4, B_*S_/128), 256>>>(Xs, 1024, fcW, 1024, fcb, enc, 512, 1024, 0);   // 1
    gemm_nt<<<dim3(H3/128, B_*S_/128), 256>>>(enc, 512, eWi, 512, ebi, gie, H3, 512, 0); // 2
    enc_pk<<<GRID, NTHR>>>(eWh, ebh);                                                    // 3 <- profile
    gather_k<<<(B_*T_*1024)/256, 256>>>(tc, 0, ce, le, Xt, B_*T_);
    startemb_k<<<64, 256>>>(ce, le, fcW, fcb, st);
    gemm_nt<<<dim3(4, B_*T_/128), 256>>>(Xt, 1024, fcW, 1024, fcb, tem, 512, 1024, 0);
    gemm_nt<<<dim3(H3/128, B_*T_/128), 256>>>(tem, 512, dWi, 1536, dbi, gid, H3, 512, 0);
    gemm_nt<<<dim3(H_/128, B_*S_/128), 256>>>(enc, 512, Wcs, 512, 0, av, H_, 512, 0);
    gemm_nt<<<dim3(H_/128, B_*S_/128), 256>>>(es, H_, Wk, H_, 0, av, H_, 1024, 1);
    tobf16_k<<<(int)(((long)B_*S_*H_ + 255)/256), 256>>>(es, es16, (long)B_*S_*H_);
    tobf16_k<<<(int)(((long)B_*S_*H_ + 255)/256), 256>>>(av, av16, (long)B_*S_*H_);
    dec_pk<<<GRID, NTHR>>>(dWi, dWh, dbi, dbh, Wq, W1, b1, W2, b2, W3, out);
}

// round 15
// speedup vs baseline: 1.5331x; 1.1749x over previous
#include <cuda_runtime.h>
#include <cuda_bf16.h>
#include <math.h>

#define B_ 32
#define S_ 512
#define T_ 128
#define H_ 1024
#define H3 3072
#define F2 4096
#define FF 2048
#define V_ 128
#define GRID 288
#define NTHR 256

typedef __nv_bfloat16 bf16;
typedef __nv_bfloat162 bf162;

__device__ float g_Xs[B_*S_*1024];
__device__ float g_Xt[B_*T_*1024];
__device__ float g_enc[B_*S_*512];
__device__ float g_tem[B_*T_*512];
__device__ float g_gie[(size_t)B_*S_*H3];
__device__ float g_gid[(size_t)B_*T_*H3];
__device__ float g_es[(size_t)B_*S_*H_];
__device__ float g_av[(size_t)B_*S_*H_];
__device__ bf16 g_es16[(size_t)B_*S_*H_];
__device__ bf16 g_av16[(size_t)B_*S_*H_];
__device__ float g_h[B_*H_];
__device__ float g_hd[B_*H_];
__device__ float g_ctA[B_*H_], g_ctB[B_*H_];
__device__ float g_ghp[12*B_*H3];
__device__ float g_cip[12*B_*H3];
__device__ float g_y1p[4*B_*F2];
__device__ float g_y2p[16*B_*FF];
__device__ float g_qp[4*B_*H_];
__device__ float g_sp[16*B_*V_];
__device__ float g_att[B_*S_];
__device__ float g_st[512];
__device__ float g_xc[B_*1536];
__device__ unsigned g_cnt;
__device__ volatile unsigned g_gen;

__device__ bf16 eWh_h[H3*H_],  eWh_l[H3*H_];
__device__ bf16 dWh_h[H3*H_],  dWh_l[H3*H_];
__device__ bf16 dWi_h[H3*1536], dWi_l[H3*1536];
__device__ bf16 Wq_h[H_*H_],   Wq_l[H_*H_];
__device__ bf16 W1_h[F2*H_],   W1_l[F2*H_];
__device__ bf16 W2_h[FF*F2],   W2_l[FF*F2];
__device__ bf16 W3_h[V_*FF],   W3_l[V_*FF];

__device__ __forceinline__ void gsync() {
    __syncthreads();
    if (threadIdx.x == 0) {
        __threadfence();
        unsigned gen = g_gen;
        if (atomicAdd(&g_cnt, 1u) == GRID - 1u) {
            g_cnt = 0;
            __threadfence();
            g_gen = gen + 1;
        } else {
            while (g_gen == gen) __nanosleep(64);
        }
        __threadfence();
    }
    __syncthreads();
}

__device__ __forceinline__ float4 loadA(const float* A0, const float* A1, int astr,
    const float* AP, long sstr, int P, const float* ab, int rl, int apN, int ar, int ko)
{
    float4 v;
    if (AP) {
        v = make_float4(0.f, 0.f, 0.f, 0.f);
        for (int p = 0; p < P; p++) {
            float4 u = *(const float4*)&AP[(long)p * sstr + (long)ar * apN + ko];
            v.x += u.x; v.y += u.y; v.z += u.z; v.w += u.w;
        }
        if (ab) { float4 u = *(const float4*)&ab[ko]; v.x += u.x; v.y += u.y; v.z += u.z; v.w += u.w; }
        if (rl) { v.x = fmaxf(v.x, 0.f); v.y = fmaxf(v.y, 0.f); v.z = fmaxf(v.z, 0.f); v.w = fmaxf(v.w, 0.f); }
    } else {
        v = *(const float4*)&A0[(long)ar * astr + ko];
        if (A1) { float4 u = *(const float4*)&A1[(long)ar * astr + ko]; v.x += u.x; v.y += u.y; v.z += u.z; v.w += u.w; }
    }
    return v;
}

__device__ __forceinline__ void split2(float2 f, unsigned& h, unsigned& l) {
    bf162 hh = __float22bfloat162_rn(f);
    float2 back = __bfloat1622float2(hh);
    bf162 ll = __float22bfloat162_rn(make_float2(f.x - back.x, f.y - back.y));
    h = *(unsigned*)&hh; l = *(unsigned*)&ll;
}

__device__ __forceinline__ void mma16816(float* d, const unsigned* a, unsigned b0, unsigned b1) {
    asm("mma.sync.aligned.m16n8k16.row.col.f32.bf16.bf16.f32 "
        "{%0,%1,%2,%3}, {%4,%5,%6,%7}, {%8,%9}, {%0,%1,%2,%3};"
        : "+f"(d[0]), "+f"(d[1]), "+f"(d[2]), "+f"(d[3])
        : "r"(a[0]), "r"(a[1]), "r"(a[2]), "r"(a[3]), "r"(b0), "r"(b1));
}

// C[32b, n0..n0+127] partial over [k0,k0+klen). bf16 hi/lo split tensor-core MMA.
__device__ __noinline__ void sgemm(float* SP,
    const float* A0, const float* A1, int astr,
    const float* AP, long sstr, int P, const float* ab, int rl, int apN,
    const bf16* Wh_, const bf16* Wl_, int ldw,
    int n0, int k0, int klen, float* C, int cN)
{
    float* As = SP;                                   // [32b][36k] fp32
    bf16* Bh = (bf16*)(SP + 1152);                    // [128n][40k]
    bf16* Bl = Bh + 128 * 40;
    int tid = threadIdx.x, lane = tid & 31, wp = tid >> 5;
    int g = lane >> 2, tg = lane & 3;
    int ar = tid >> 3, kq = (tid & 7) * 4;            // A loader
    int wr = tid >> 1, whf = (tid & 1) * 16;          // W loader: 16 elems each
    float acc[2][2][4] = {};
    float4 apre; uint4 wh4a, wh4b, wl4a, wl4b;

    apre = loadA(A0, A1, astr, AP, sstr, P, ab, rl, apN, ar, k0 + kq);
    {
        const bf16* ph = &Wh_[(long)(n0 + wr) * ldw + k0 + whf];
        const bf16* pl = &Wl_[(long)(n0 + wr) * ldw + k0 + whf];
        wh4a = *(const uint4*)ph; wh4b = *(const uint4*)(ph + 8);
        wl4a = *(const uint4*)pl; wl4b = *(const uint4*)(pl + 8);
    }

    for (int kk = k0; kk < k0 + klen; kk += 32) {
        __syncthreads();
        *(float4*)&As[ar * 36 + kq] = apre;
        *(uint4*)((char*)Bh + (wr * 40 + whf) * 2) = wh4a;
        *(uint4*)((char*)Bh + (wr * 40 + whf + 8) * 2) = wh4b;
        *(uint4*)((char*)Bl + (wr * 40 + whf) * 2) = wl4a;
        *(uint4*)((char*)Bl + (wr * 40 + whf + 8) * 2) = wl4b;
        __syncthreads();
        int kn = kk + 32;
        if (kn < k0 + klen) {
            apre = loadA(A0, A1, astr, AP, sstr, P, ab, rl, apN, ar, kn + kq);
            const bf16* ph = &Wh_[(long)(n0 + wr) * ldw + kn + whf];
            const bf16* pl = &Wl_[(long)(n0 + wr) * ldw + kn + whf];
            wh4a = *(const uint4*)ph; wh4b = *(const uint4*)(ph + 8);
            wl4a = *(const uint4*)pl; wl4b = *(const uint4*)(pl + 8);
        }
#pragma unroll
        for (int s16 = 0; s16 < 32; s16 += 16) {
            unsigned aH[2][4], aL[2][4];
#pragma unroll
            for (int m = 0; m < 2; m++) {
                int r0 = m * 16 + g, r1 = r0 + 8;
                float2 f0 = *(float2*)&As[r0 * 36 + s16 + 2 * tg];
                float2 f1 = *(float2*)&As[r1 * 36 + s16 + 2 * tg];
                float2 f2 = *(float2*)&As[r0 * 36 + s16 + 2 * tg + 8];
                float2 f3 = *(float2*)&As[r1 * 36 + s16 + 2 * tg + 8];
                split2(f0, aH[m][0], aL[m][0]);
                split2(f1, aH[m][1], aL[m][1]);
                split2(f2, aH[m][2], aL[m][2]);
                split2(f3, aH[m][3], aL[m][3]);
            }
#pragma unroll
            for (int nt = 0; nt < 2; nt++) {
                int nr = wp * 16 + nt * 8 + g;
                unsigned bh0 = *(unsigned*)&Bh[nr * 40 + s16 + 2 * tg];
                unsigned bh1 = *(unsigned*)&Bh[nr * 40 + s16 + 2 * tg + 8];
                unsigned bl0 = *(unsigned*)&Bl[nr * 40 + s16 + 2 * tg];
                unsigned bl1 = *(unsigned*)&Bl[nr * 40 + s16 + 2 * tg + 8];
#pragma unroll
                for (int m = 0; m < 2; m++) {
                    mma16816(acc[m][nt], aH[m], bh0, bh1);
                    mma16816(acc[m][nt], aH[m], bl0, bl1);
                    mma16816(acc[m][nt], aL[m], bh0, bh1);
                }
            }
        }
    }
#pragma unroll
    for (int m = 0; m < 2; m++)
#pragma unroll
        for (int nt = 0; nt < 2; nt++) {
            int col = n0 + wp * 16 + nt * 8 + 2 * tg;
            *(float2*)&C[(long)(m * 16 + g) * cN + col] = make_float2(acc[m][nt][0], acc[m][nt][1]);
            *(float2*)&C[(long)(m * 16 + g + 8) * cN + col] = make_float2(acc[m][nt][2], acc[m][nt][3]);
        }
}

__global__ void wsplit_k(const float* __restrict__ src, bf16* __restrict__ h,
                         bf16* __restrict__ l, long n) {
    long i = (long)blockIdx.x * 256 + threadIdx.x;
    if (i < n) {
        float x = src[i];
        bf16 hi = __float2bfloat16(x);
        h[i] = hi;
        l[i] = __float2bfloat16(x - __bfloat162float(hi));
    }
}

__global__ void gather_k(const int* __restrict__ ch, const int* __restrict__ lg,
                         const float* __restrict__ ce, const float* __restrict__ le,
                         float* __restrict__ X, int ntok) {
    long i = (long)blockIdx.x * 256 + threadIdx.x;
    if (i >= (long)ntok * 1024) return;
    int tok = (int)(i >> 10), c = (int)(i & 1023);
    X[i] = (c < 512) ? ce[ch[tok] * 512 + c] : le[(lg ? lg[tok] : 4) * 512 + (c - 512)];
}

__global__ void startemb_k(const float* __restrict__ ce, const float* __restrict__ le,
                           const float* __restrict__ fcW, const float* __restrict__ fcb,
                           float* __restrict__ o) {
    int g = blockIdx.x * 8 + (threadIdx.x >> 5), l = threadIdx.x & 31;
    float a = 0.f;
    for (int k = l; k < 1024; k += 32)
        a += ((k < 512) ? ce[512 + k] : le[2048 + (k - 512)]) * fcW[g * 1024 + k];
#pragma unroll
    for (int s = 16; s; s >>= 1) a += __shfl_down_sync(~0u, a, s);
    if (!l) o[g] = a + fcb[g];
}

__global__ void tobf16_k(const float* __restrict__ src, bf16* __restrict__ dst, long n) {
    long i = (long)blockIdx.x * 256 + threadIdx.x;
    if (i < n) dst[i] = __float2bfloat16(src[i]);
}

__global__ void gemm_nt(const float* __restrict__ A, int lda,
                        const float* __restrict__ W, int ldw,
                        const float* __restrict__ bias,
                        float* __restrict__ C, int ldc, int K, int accf) {
    __shared__ float As[8][128], Ws[8][128];
    int bm = blockIdx.y * 128, bn = blockIdx.x * 128, tid = threadIdx.x;
    int lr = tid >> 1, lc = (tid & 1) * 4, tx = tid & 15, ty = tid >> 4;
    float acc[8][8] = {};
    for (int k0 = 0; k0 < K; k0 += 8) {
        float4 a = *(const float4*)&A[(long)(bm + lr) * lda + k0 + lc];
        float4 w = *(const float4*)&W[(long)(bn + lr) * ldw + k0 + lc];
        As[lc][lr] = a.x; As[lc+1][lr] = a.y; As[lc+2][lr] = a.z; As[lc+3][lr] = a.w;
        Ws[lc][lr] = w.x; Ws[lc+1][lr] = w.y; Ws[lc+2][lr] = w.z; Ws[lc+3][lr] = w.w;
        __syncthreads();
#pragma unroll
        for (int k = 0; k < 8; k++) {
            float avv[8], bv[8];
            *(float4*)avv = *(const float4*)&As[k][ty*8]; *(float4*)(avv+4) = *(const float4*)&As[k][ty*8+4];
            *(float4*)bv = *(const float4*)&Ws[k][tx*8]; *(float4*)(bv+4) = *(const float4*)&Ws[k][tx*8+4];
#pragma unroll
            for (int i = 0; i < 8; i++)
#pragma unroll
                for (int j = 0; j < 8; j++) acc[i][j] = fmaf(avv[i], bv[j], acc[i][j]);
        }
        __syncthreads();
    }
#pragma unroll
    for (int i = 0; i < 8; i++) {
        long row = bm + ty * 8 + i;
#pragma unroll
        for (int j = 0; j < 8; j += 4) {
            int col = bn + tx * 8 + j;
            float4 v = make_float4(acc[i][j], acc[i][j+1], acc[i][j+2], acc[i][j+3]);
            if (bias) { v.x += bias[col]; v.y += bias[col+1]; v.z += bias[col+2]; v.w += bias[col+3]; }
            float4* cp = (float4*)&C[row * ldc + col];
            if (accf) { float4 o = *cp; v.x += o.x; v.y += o.y; v.z += o.z; v.w += o.w; }
            *cp = v;
        }
    }
}

__global__ void __launch_bounds__(NTHR, 2) enc_pk(const float* __restrict__ bh) {
    __shared__ __align__(16) float SP[6272];
    int bid = blockIdx.x, tid = threadIdx.x;
    for (int i = bid * NTHR + tid; i < B_ * H_; i += GRID * NTHR) g_h[i] = 0.f;
    gsync();
    const int kb[13] = {0,96,192,288,384,480,576,672,768,832,896,960,1024};
    int nt = bid / 12, ks = bid % 12;
    for (int t = 0; t < S_; t++) {
        sgemm(SP, g_h, 0, H_, 0, 0, 0, 0, 0, 0, eWh_h, eWh_l, H_, nt * 128, kb[ks], kb[ks+1] - kb[ks],
              g_ghp + (long)ks * B_ * H3, H3);
        gsync();
        for (int i = bid * NTHR + tid; i < B_ * H_; i += GRID * NTHR) {
            int b = i >> 10, j = i & 1023;
            const float* gi = &g_gie[((size_t)(b * S_ + t)) * H3];
            float ir = gi[j], iz = gi[j + H_], in = gi[j + 2*H_];
            float hr = bh[j], hz = bh[j + H_], hn = bh[j + 2*H_];
            for (int p = 0; p < 12; p++) {
                const float* gp = &g_ghp[(long)p * B_ * H3 + (long)b * H3];
                hr += gp[j]; hz += gp[j + H_]; hn += gp[j + 2*H_];
            }
            float ho = g_h[i];
            float r = 1.f / (1.f + expf(-(ir + hr)));
            float z = 1.f / (1.f + expf(-(iz + hz)));
            float n = tanhf(in + r * hn);
            float hv = (1.f - z) * n + z * ho;
            g_h[i] = hv;
            g_es[((size_t)(b * S_ + t)) * H_ + j] = hv;
        }
        gsync();
    }
}

__global__ void __launch_bounds__(NTHR, 2) dec_pk(
    const float* __restrict__ bi, const float* __restrict__ bh,
    const float* __restrict__ b1, const float* __restrict__ b2,
    float* __restrict__ out) {
    __shared__ __align__(16) float SP[6272];
    int bid = blockIdx.x, tid = threadIdx.x;
    for (int i = bid * NTHR + tid; i < B_ * 1536; i += GRID * NTHR) {
        int b = i / 1536, k = i % 1536;
        float v = (k < 512) ? g_st[k] : g_es[((size_t)(b * S_ + S_ - 1)) * H_ + k - 512];
        if (k >= 512) g_ctA[b * H_ + k - 512] = v;
        g_xc[i] = v;
    }
    gsync();
    { int nt = bid / 12, ks = bid % 12;
      sgemm(SP, g_xc, 0, 1536, 0, 0, 0, 0, 0, 0, dWi_h, dWi_l, 1536, nt * 128, ks * 128, 128,
            g_cip + (long)ks * B_ * H3, H3); }
    gsync();
    for (int i = bid * NTHR + tid; i < B_ * H_; i += GRID * NTHR) {
        int b = i >> 10, j = i & 1023;
        float ir = bi[j], iz = bi[j + H_], in = bi[j + 2*H_];
        for (int p = 0; p < 12; p++) {
            const float* gp = &g_cip[(long)p * B_ * H3 + (long)b * H3];
            ir += gp[j]; iz += gp[j + H_]; in += gp[j + 2*H_];
        }
        float hr = bh[j], hz = bh[j + H_], hn = bh[j + 2*H_];
        float r = 1.f / (1.f + expf(-(ir + hr)));
        float z = 1.f / (1.f + expf(-(iz + hz)));
        float n = tanhf(in + r * hn);
        g_hd[i] = (1.f - z) * n;
    }
    gsync();
    for (int t = 0; t < T_; t++) {
        const float* cp = (t & 1) ? g_ctB : g_ctA;
        float* cn = (t & 1) ? g_ctA : g_ctB;
        for (int it = bid; it < 256; it += GRID) {           // S1
            if (it < 128) { int nt = it >> 2, ks = it & 3;
                sgemm(SP, g_hd, cp, H_, 0,0,0,0,0,0, W1_h, W1_l, H_, nt*128, ks*256, 256, g_y1p + (long)ks*B_*F2, F2); }
            else if (it < 160) { int i2 = it - 128, nt = i2 >> 2, ks = i2 & 3;
                sgemm(SP, g_hd, 0, H_, 0,0,0,0,0,0, Wq_h, Wq_l, H_, nt*128, ks*256, 256, g_qp + (long)ks*B_*H_, H_); }
            else { int i2 = it - 160, nt = i2 >> 2, ks = i2 & 3;
                sgemm(SP, g_hd, 0, H_, 0,0,0,0,0,0, dWh_h, dWh_l, H_, nt*128, ks*256, 256, g_ghp + (long)ks*B_*H3, H3); }
        }
        gsync();
        for (int it = bid; it < 288; it += GRID) {           // S2
            if (it < 256) { int nt = it >> 4, ks = it & 15;
                sgemm(SP, 0,0,0, g_y1p, (long)B_*F2, 4, b1, 1, F2, W2_h, W2_l, F2, nt*128, ks*256, 256,
                      g_y2p + (long)ks*B_*FF, FF); }
            else {
                int b = it - 256;
                float* q = SP;
                __syncthreads();
                for (int i = tid; i < H_; i += NTHR) {
                    float s = 0.f;
                    for (int p = 0; p < 4; p++) s += g_qp[(long)p*B_*H_ + b*H_ + i];
                    q[i] = s;
                }
                __syncthreads();
                int w = tid >> 5, l = tid & 31;
                for (int s = w; s < S_; s += 8) {
                    const bf16* e = &g_es16[((size_t)(b * S_ + s)) * H_];
                    float a = 0.f;
#pragma unroll
                    for (int m = 0; m < 4; m++) {
                        const bf162* e2 = (const bf162*)&e[m*256 + l*8];
                        const float* qq = &q[m*256 + l*8];
#pragma unroll
                        for (int u = 0; u < 4; u++) {
                            float2 p = __bfloat1622float2(e2[u]);
                            a += p.x * qq[u*2] + p.y * qq[u*2+1];
                        }
                    }
#pragma unroll
                    for (int o = 16; o; o >>= 1) a += __shfl_down_sync(~0u, a, o);
                    if (!l) g_att[b * S_ + s] = a;
                }
                __syncthreads();
            }
        }
        gsync();
        for (int it = bid; it < 144; it += GRID) {           // S3
            if (it < 128) {
                int b = it >> 2, hq = it & 3;
                float* red = SP + 512;
                __syncthreads();
                float v0 = g_att[b*S_ + tid], v1 = g_att[b*S_ + 256 + tid];
                red[tid] = fmaxf(v0, v1); __syncthreads();
                for (int s = 128; s; s >>= 1) { if (tid < s) red[tid] = fmaxf(red[tid], red[tid+s]); __syncthreads(); }
                float mx = red[0]; __syncthreads();
                float e0 = expf(v0 - mx), e1 = expf(v1 - mx);
                red[tid] = e0 + e1; __syncthreads();
                for (int s = 128; s; s >>= 1) { if (tid < s) red[tid] += red[tid+s]; __syncthreads(); }
                float inv = 1.f / red[0]; __syncthreads();
                SP[tid] = e0 * inv; SP[tid + 256] = e1 * inv;
                __syncthreads();
                int hc = hq * 256 + tid;
                const bf16* a = &g_av16[((size_t)b * S_) * H_ + hc];
                float acc = 0.f;
#pragma unroll 8
                for (int s = 0; s < S_; s++) acc += SP[s] * __bfloat162float(a[(size_t)s * H_]);
                cn[b * H_ + hc] = acc;
                __syncthreads();
            } else { int ks = it - 128;
                sgemm(SP, 0,0,0, g_y2p, (long)B_*FF, 16, b2, 1, FF, W3_h, W3_l, FF, 0, ks*128, 128,
                      g_sp + (long)ks*B_*V_, V_); }
        }
        gsync();
        for (int it = bid; it < 192; it += GRID) {           // S4
            int nt = it >> 3, ks = it & 7;
            sgemm(SP, cn, 0, H_, 0,0,0,0,0,0, dWi_h + 512, dWi_l + 512, 1536, nt*128, ks*128, 128,
                  g_cip + (long)ks*B_*H3, H3);
        }
        gsync();
        for (int i = bid * NTHR + tid; i < B_ * H_; i += GRID * NTHR) {   // S5
            int b = i >> 10, j = i & 1023;
            const float* gi = &g_gid[((size_t)(b * T_ + t)) * H3];
            float ir = gi[j], iz = gi[j + H_], in = gi[j + 2*H_];
            for (int p = 0; p < 8; p++) {
                const float* gp = &g_cip[(long)p*B_*H3 + (long)b*H3];
                ir += gp[j]; iz += gp[j + H_]; in += gp[j + 2*H_];
            }
            float hr = bh[j], hz = bh[j + H_], hn = bh[j + 2*H_];
            for (int p = 0; p < 4; p++) {
                const float* gp = &g_ghp[(long)p*B_*H3 + (long)b*H3];
                hr += gp[j]; hz += gp[j + H_]; hn += gp[j + 2*H_];
            }
            float ho = g_hd[i];
            float r = 1.f / (1.f + expf(-(ir + hr)));
            float z = 1.f / (1.f + expf(-(iz + hz)));
            float n = tanhf(in + r * hn);
            g_hd[i] = (1.f - z) * n + z * ho;
        }
        for (int i = bid * NTHR + tid; i < B_ * V_; i += GRID * NTHR) {
            int b = i >> 7, v = i & 127;
            float s = 0.f;
            for (int p = 0; p < 16; p++) s += g_sp[p*B_*V_ + b*V_ + v];
            out[((size_t)(b * T_ + t)) * V_ + v] = s;
        }
        gsync();
    }
}

static float* sym(const void* s) { void* p = 0; cudaGetSymbolAddress(&p, s); return (float*)p; }
static bf16* symb(const void* s) { void* p = 0; cudaGetSymbolAddress(&p, s); return (bf16*)p; }
#define WSPLIT(w, hh, ll, n) wsplit_k<<<(int)(((long)(n)+255)/256), 256>>>(w, symb(hh), symb(ll), (long)(n))

extern "C" void kernel_launch(void* const* d_in, const int*, int, void* d_out, int) {
    const int* sc = (const int*)d_in[0];  const int* sl = (const int*)d_in[1];
    const int* tc = (const int*)d_in[2];
    const float* ce = (const float*)d_in[3];  const float* le = (const float*)d_in[4];
    const float* fcW = (const float*)d_in[5]; const float* fcb = (const float*)d_in[6];
    const float* eWi = (const float*)d_in[7]; const float* eWh = (const float*)d_in[8];
    const float* ebi = (const float*)d_in[9]; const float* ebh = (const float*)d_in[10];
    const float* dWi = (const float*)d_in[11]; const float* dWh = (const float*)d_in[12];
    const float* dbi = (const float*)d_in[13]; const float* dbh = (const float*)d_in[14];
    const float* Wq = (const float*)d_in[15]; const float* Wk = (const float*)d_in[16];
    const float* Wcs = (const float*)d_in[17];
    const float* W1 = (const float*)d_in[18]; const float* b1 = (const float*)d_in[19];
    const float* W2 = (const float*)d_in[20]; const float* b2 = (const float*)d_in[21];
    const float* W3 = (const float*)d_in[22];
    float* out = (float*)d_out;
    float *Xs = sym(g_Xs), *Xt = sym(g_Xt), *enc = sym(g_enc), *tem = sym(g_tem),
          *gie = sym(g_gie), *gid = sym(g_gid), *es = sym(g_es), *av = sym(g_av), *st = sym(g_st);
    bf16 *es16 = symb(g_es16), *av16 = symb(g_av16);

    WSPLIT(eWh, eWh_h, eWh_l, H3*H_);
    gather_k<<<(B_*S_*1024)/256, 256>>>(sc, sl, ce, le, Xs, B_*S_);
    gemm_nt<<<dim3(4, B_*S_/128), 256>>>(Xs, 1024, fcW, 1024, fcb, enc, 512, 1024, 0);
    gemm_nt<<<dim3(H3/128, B_*S_/128), 256>>>(enc, 512, eWi, 512, ebi, gie, H3, 512, 0);
    enc_pk<<<GRID, NTHR>>>(ebh);
    WSPLIT(dWh, dWh_h, dWh_l, H3*H_);
    WSPLIT(dWi, dWi_h, dWi_l, H3*1536);
    WSPLIT(Wq, Wq_h, Wq_l, H_*H_);
    WSPLIT(W1, W1_h, W1_l, F2*H_);
    WSPLIT(W2, W2_h, W2_l, FF*F2);
    WSPLIT(W3, W3_h, W3_l, V_*FF);
    gather_k<<<(B_*T_*1024)/256, 256>>>(tc, 0, ce, le, Xt, B_*T_);
    startemb_k<<<64, 256>>>(ce, le, fcW, fcb, st);
    gemm_nt<<<dim3(4, B_*T_/128), 256>>>(Xt, 1024, fcW, 1024, fcb, tem, 512, 1024, 0);
    gemm_nt<<<dim3(H3/128, B_*T_/128), 256>>>(tem, 512, dWi, 1536, dbi, gid, H3, 512, 0);
    gemm_nt<<<dim3(H_/128, B_*S_/128), 256>>>(enc, 512, Wcs, 512, 0, av, H_, 512, 0);
    gemm_nt<<<dim3(H_/128, B_*S_/128), 256>>>(es, H_, Wk, H_, 0, av, H_, 1024, 1);
    tobf16_k<<<(int)(((long)B_*S_*H_ + 255)/256), 256>>>(es, es16, (long)B_*S_*H_);
    tobf16_k<<<(int)(((long)B_*S_*H_ + 255)/256), 256>>>(av, av16, (long)B_*S_*H_);
    dec_pk<<<GRID, NTHR>>>(dbi, dbh, b1, b2, out);
}